// round 10
// baseline (speedup 1.0000x reference)
#include <cuda_runtime.h>
#include <cuda_bf16.h>
#include <math.h>
#include <stdint.h>

#define NROWS 65536
#define KC 256
#define DH 256
#define NKSZ ((size_t)NROWS * KC)
#define EPSV 1e-6f
#define SIGMA_HI_V 10000.0f
#define TARGET_Z 1.3219281f   /* log2(5)-1 */
#define TARGET_U 2.3219281f   /* log2(5)   */
#define INF_F __int_as_float(0x7f800000)
#define CAL_ITERS 64
#define NPART 2048

// ---------------- scratch (device globals; no runtime allocation) ----------
__device__ float g_d[NKSZ];                 // 64MB distance matrix
__device__ uint4 g_mhi4[KC * 64];           // mu hi tf32-in-f32 (16B quads)
__device__ uint4 g_mlo4[KC * 64];           // mu lo tf32-in-f32
__device__ float g_m2[KC], g_ms[KC];
__device__ float g_rowp[(size_t)2 * NROWS * 5];  // per-colhalf row top5 partials
__device__ float g_rhoz[NROWS];
__device__ float g_sigz[NROWS];
__device__ float g_part1[(size_t)NPART * 5 * KC];   // [chunk][s][col]
__device__ float g_rhou[KC];
__device__ float g_sigu[KC];
__device__ float g_colsum[KC];

// ---------------- PTX helpers (baseline PTX only) ----------------------------
__device__ __forceinline__ uint32_t smem_u32(const void* p) {
    uint32_t a;
    asm("{ .reg .u64 t; cvta.to.shared.u64 t, %1; cvt.u32.u64 %0, t; }" : "=r"(a) : "l"(p));
    return a;
}

__device__ __forceinline__ uint32_t tf32u(float x) {
    uint32_t u;
    asm("cvt.rna.tf32.f32 %0, %1;" : "=r"(u) : "f"(x));
    return u;
}

__device__ __forceinline__ void ldmx4(uint32_t* r, uint32_t addr) {
    asm volatile("ldmatrix.sync.aligned.m8n8.x4.shared.b16 {%0,%1,%2,%3}, [%4];"
                 : "=r"(r[0]), "=r"(r[1]), "=r"(r[2]), "=r"(r[3]) : "r"(addr));
}

__device__ __forceinline__ void mma_tf32(float* d, const uint32_t* a, const uint32_t* b) {
    asm volatile(
        "mma.sync.aligned.m16n8k8.row.col.f32.tf32.tf32.f32 "
        "{%0,%1,%2,%3}, {%4,%5,%6,%7}, {%8,%9}, {%0,%1,%2,%3};"
        : "+f"(d[0]), "+f"(d[1]), "+f"(d[2]), "+f"(d[3])
        : "r"(a[0]), "r"(a[1]), "r"(a[2]), "r"(a[3]), "r"(b[0]), "r"(b[1]));
}

// ---------------- K0: mu prep (hi/lo tf32 split + stats) ---------------------
__global__ void k_prep_mu(const float* __restrict__ mu) {
    int j = threadIdx.x;
    const float* r = mu + (size_t)j * DH;
    float m2 = 0.f, ms = 0.f;
    for (int i = 0; i < 64; i++) {
        float4 v = *(const float4*)(r + i * 4);
        float x[4] = {v.x, v.y, v.z, v.w};
        uint32_t hi[4], lo[4];
#pragma unroll
        for (int q = 0; q < 4; q++) {
            m2 = fmaf(x[q], x[q], m2);
            ms += x[q];
            hi[q] = tf32u(x[q]);
            lo[q] = tf32u(x[q] - __uint_as_float(hi[q]));
        }
        g_mhi4[j * 64 + i] = make_uint4(hi[0], hi[1], hi[2], hi[3]);
        g_mlo4[j * 64 + i] = make_uint4(lo[0], lo[1], lo[2], lo[3]);
    }
    g_m2[j] = m2;
    g_ms[j] = ms;
}

// ---------------- K-zero / K-noop (pad launch order for profiling) ----------
__global__ void k_zero() { g_colsum[threadIdx.x] = 0.f; }
__global__ void k_noop() {}

// ---------------- insertion helper ------------------------------------------
__device__ __forceinline__ void ins5(float v, float &t0, float &t1, float &t2,
                                     float &t3, float &t4) {
    if (v < t4) {
        if (v < t3) {
            t4 = t3;
            if (v < t2) {
                t3 = t2;
                if (v < t1) {
                    t2 = t1;
                    if (v < t0) { t1 = t0; t0 = v; } else t1 = v;
                } else t2 = v;
            } else t3 = v;
        } else t4 = v;
    }
}

// ---------------- K1: fused tf32-split GEMM + d + row/col top5 ---------------
// CTA: 128 z-rows x 128 mu-cols, 512 threads = 16 warps (4x4).
// Warp tile 32x32 (acc = 32 regs -> no spills). K in 4 chunks of 64.
// 3 passes hh+lh+hl; m16n8k8 tf32 mma, fp32 accum.
#define LDS_A 68                      /* padded f32 row stride (64+4) */
#define TILE_LD 132                   /* padded f32 tile stride */
#define SA_HI 0
#define SA_LO 34816
#define SB_HI 69632
#define SB_LO 104448
#define ST_M2 139264
#define ST_MS 139776
#define ST_Z2 140288
#define ST_ZS 140800
#define GSMEM_TOTAL 141312

__global__ __launch_bounds__(512, 1) void k_gemm(const float* __restrict__ z) {
    extern __shared__ char smem[];
    const uint32_t sb = smem_u32(smem);
    const int t = threadIdx.x;
    const int wid = t >> 5, lane = t & 31;
    const int wr = wid >> 2, wc = wid & 3;
    const int rowBase = blockIdx.x * 128;
    const int colBase = blockIdx.y * 128;

    float* s_m2 = (float*)(smem + ST_M2);
    float* s_ms = (float*)(smem + ST_MS);
    float* s_z2 = (float*)(smem + ST_Z2);
    float* s_zs = (float*)(smem + ST_ZS);
    if (t < 128) { s_m2[t] = g_m2[colBase + t]; s_ms[t] = g_ms[colBase + t]; }

    float acc[2][4][4];
#pragma unroll
    for (int mt = 0; mt < 2; mt++)
#pragma unroll
        for (int j = 0; j < 4; j++)
#pragma unroll
            for (int q = 0; q < 4; q++) acc[mt][j][q] = 0.f;

    // A loader mapping: thread -> (row = t/4, 16-col segment aq = t%4)
    const int ar = t >> 2, aq = t & 3;
    const float* zrow = z + (size_t)(rowBase + ar) * DH + aq * 16;
    float z2p = 0.f, zsp = 0.f;

    // ldmatrix lane address components (f32 tiles: 8 rows x 4 f32-cols)
    const uint32_t a_off = ((uint32_t)(wr * 32 + (lane & 15)) * LDS_A +
                            ((lane >> 4) << 2)) * 4;
    const uint32_t b_off = ((uint32_t)(wc * 32 + ((lane >> 4) << 3) + (lane & 7)) * LDS_A +
                            ((lane & 8) >> 1)) * 4;

#pragma unroll 1
    for (int c = 0; c < 4; c++) {
        __syncthreads();
        // ---- A: stream-load z fp32 in groups of 4 (low reg pressure) --------
        {
            const float4* src = (const float4*)(zrow + c * 64);
            uint32_t off = ((uint32_t)ar * LDS_A + aq * 16) * 4;
#pragma unroll
            for (int g = 0; g < 4; g++) {
                float4 v = src[g];
                z2p = fmaf(v.x, v.x, fmaf(v.y, v.y, fmaf(v.z, v.z, fmaf(v.w, v.w, z2p))));
                zsp += v.x + v.y + v.z + v.w;
                float4 hv = make_float4(
                    __uint_as_float(tf32u(v.x)), __uint_as_float(tf32u(v.y)),
                    __uint_as_float(tf32u(v.z)), __uint_as_float(tf32u(v.w)));
                float4 lv = make_float4(
                    __uint_as_float(tf32u(v.x - hv.x)), __uint_as_float(tf32u(v.y - hv.y)),
                    __uint_as_float(tf32u(v.z - hv.z)), __uint_as_float(tf32u(v.w - hv.w)));
                *(float4*)(smem + SA_HI + off + g * 16) = hv;
                *(float4*)(smem + SA_LO + off + g * 16) = lv;
            }
        }
        // ---- B: copy pre-converted mu hi/lo quads (128 rows x 16 uint4) -----
#pragma unroll
        for (int i = 0; i < 4; i++) {
            int e = t + 512 * i;             // 0..2047
            int row = e >> 4, q = e & 15;
            uint32_t off = ((uint32_t)row * LDS_A + q * 4) * 4;
            *(uint4*)(smem + SB_HI + off) = g_mhi4[(colBase + row) * 64 + c * 16 + q];
            *(uint4*)(smem + SB_LO + off) = g_mlo4[(colBase + row) * 64 + c * 16 + q];
        }
        __syncthreads();

        // ---- mma over 8 k8-steps ----------------------------------------------
#pragma unroll
        for (int ks = 0; ks < 8; ks++) {
            const uint32_t kb = (uint32_t)ks * 32;
            uint32_t ah[2][4], al[2][4];
            ldmx4(ah[0], sb + SA_HI + a_off + kb);
            ldmx4(ah[1], sb + SA_HI + a_off + kb + 16 * LDS_A * 4);
            ldmx4(al[0], sb + SA_LO + a_off + kb);
            ldmx4(al[1], sb + SA_LO + a_off + kb + 16 * LDS_A * 4);

            uint32_t bh0[4], bh1[4];
            ldmx4(bh0, sb + SB_HI + b_off + kb);
            ldmx4(bh1, sb + SB_HI + b_off + kb + 16 * LDS_A * 4);
            // hh pass
            mma_tf32(acc[0][0], ah[0], &bh0[0]);
            mma_tf32(acc[0][1], ah[0], &bh0[2]);
            mma_tf32(acc[1][0], ah[1], &bh0[0]);
            mma_tf32(acc[1][1], ah[1], &bh0[2]);
            mma_tf32(acc[0][2], ah[0], &bh1[0]);
            mma_tf32(acc[0][3], ah[0], &bh1[2]);
            mma_tf32(acc[1][2], ah[1], &bh1[0]);
            mma_tf32(acc[1][3], ah[1], &bh1[2]);
            // lo B prefetch (latency hidden under lh pass)
            uint32_t bl0[4], bl1[4];
            ldmx4(bl0, sb + SB_LO + b_off + kb);
            ldmx4(bl1, sb + SB_LO + b_off + kb + 16 * LDS_A * 4);
            // lh pass
            mma_tf32(acc[0][0], al[0], &bh0[0]);
            mma_tf32(acc[0][1], al[0], &bh0[2]);
            mma_tf32(acc[1][0], al[1], &bh0[0]);
            mma_tf32(acc[1][1], al[1], &bh0[2]);
            mma_tf32(acc[0][2], al[0], &bh1[0]);
            mma_tf32(acc[0][3], al[0], &bh1[2]);
            mma_tf32(acc[1][2], al[1], &bh1[0]);
            mma_tf32(acc[1][3], al[1], &bh1[2]);
            // hl pass
            mma_tf32(acc[0][0], ah[0], &bl0[0]);
            mma_tf32(acc[0][1], ah[0], &bl0[2]);
            mma_tf32(acc[1][0], ah[1], &bl0[0]);
            mma_tf32(acc[1][1], ah[1], &bl0[2]);
            mma_tf32(acc[0][2], ah[0], &bl1[0]);
            mma_tf32(acc[0][3], ah[0], &bl1[2]);
            mma_tf32(acc[1][2], ah[1], &bl1[0]);
            mma_tf32(acc[1][3], ah[1], &bl1[2]);
        }
    }

    // ---- finalize per-row z stats (4 loader threads per row) ---------------
    z2p += __shfl_xor_sync(0xffffffffu, z2p, 1);
    z2p += __shfl_xor_sync(0xffffffffu, z2p, 2);
    zsp += __shfl_xor_sync(0xffffffffu, zsp, 1);
    zsp += __shfl_xor_sync(0xffffffffu, zsp, 2);
    if (aq == 0) { s_z2[ar] = z2p; s_zs[ar] = zsp; }
    __syncthreads();

    // ---- epilogue: d into smem tile (overwrites A/B buffers) ----------------
    float* tile = (float*)smem;
    const float cterm = (float)DH * EPSV * EPSV;
#pragma unroll
    for (int mt = 0; mt < 2; mt++) {
        const int r0 = wr * 32 + mt * 16 + (lane >> 2);
        const float z2va = s_z2[r0], zsva = s_zs[r0];
        const float z2vb = s_z2[r0 + 8], zsvb = s_zs[r0 + 8];
#pragma unroll
        for (int nt = 0; nt < 4; nt++) {
            const int c0 = wc * 32 + nt * 8 + (lane & 3) * 2;
            float m20 = s_m2[c0], ms0 = s_ms[c0];
            float m21 = s_m2[c0 + 1], ms1 = s_ms[c0 + 1];
            float d00 = z2va + m20 - 2.f * acc[mt][nt][0] + 2.f * EPSV * (zsva - ms0) + cterm;
            float d01 = z2va + m21 - 2.f * acc[mt][nt][1] + 2.f * EPSV * (zsva - ms1) + cterm;
            float d10 = z2vb + m20 - 2.f * acc[mt][nt][2] + 2.f * EPSV * (zsvb - ms0) + cterm;
            float d11 = z2vb + m21 - 2.f * acc[mt][nt][3] + 2.f * EPSV * (zsvb - ms1) + cterm;
            tile[r0 * TILE_LD + c0]           = sqrtf(fmaxf(d00, 0.f));
            tile[r0 * TILE_LD + c0 + 1]       = sqrtf(fmaxf(d01, 0.f));
            tile[(r0 + 8) * TILE_LD + c0]     = sqrtf(fmaxf(d10, 0.f));
            tile[(r0 + 8) * TILE_LD + c0 + 1] = sqrtf(fmaxf(d11, 0.f));
        }
    }
    __syncthreads();

    // ---- coalesced store of d ------------------------------------------------
#pragma unroll
    for (int i = 0; i < 8; i++) {
        int e = t + 512 * i;          // 0..4095
        int row = e >> 5, c4 = e & 31;
        float4 v = *(const float4*)&tile[row * TILE_LD + c4 * 4];
        *(float4*)&g_d[(size_t)(rowBase + row) * KC + colBase + c4 * 4] = v;
    }

    // ---- row top-5 partials (this CTA's 128 cols; warp per 8 rows) ------------
#pragma unroll 1
    for (int rr = 0; rr < 8; rr++) {
        int lrow = wid * 8 + rr;
        float t0 = INF_F, t1 = INF_F, t2 = INF_F, t3 = INF_F, t4 = INF_F;
#pragma unroll
        for (int i = 0; i < 4; i++)
            ins5(tile[lrow * TILE_LD + lane + 32 * i], t0, t1, t2, t3, t4);
#pragma unroll
        for (int off = 16; off; off >>= 1) {
            float o0 = __shfl_xor_sync(0xffffffffu, t0, off);
            float o1 = __shfl_xor_sync(0xffffffffu, t1, off);
            float o2 = __shfl_xor_sync(0xffffffffu, t2, off);
            float o3 = __shfl_xor_sync(0xffffffffu, t3, off);
            float o4 = __shfl_xor_sync(0xffffffffu, t4, off);
            ins5(o0, t0, t1, t2, t3, t4);
            ins5(o1, t0, t1, t2, t3, t4);
            ins5(o2, t0, t1, t2, t3, t4);
            ins5(o3, t0, t1, t2, t3, t4);
            ins5(o4, t0, t1, t2, t3, t4);
        }
        if (lane == 0) {
            float* rp = g_rowp + (size_t)blockIdx.y * NROWS * 5 +
                        (size_t)(rowBase + lrow) * 5;
            rp[0] = t0; rp[1] = t1; rp[2] = t2; rp[3] = t3; rp[4] = t4;
        }
    }

    // ---- column top-5 partials (4 row-quarters of 32) --------------------------
    {
        int colL = t & 127, qtr = t >> 7;
        float t0 = INF_F, t1 = INF_F, t2 = INF_F, t3 = INF_F, t4 = INF_F;
#pragma unroll 4
        for (int r = 0; r < 32; r++)
            ins5(tile[(qtr * 32 + r) * TILE_LD + colL], t0, t1, t2, t3, t4);
        int p = blockIdx.x * 4 + qtr;
        float* pp = g_part1 + (size_t)p * 5 * KC + colBase + colL;
        pp[0 * KC] = t0; pp[1 * KC] = t1; pp[2 * KC] = t2;
        pp[3 * KC] = t3; pp[4 * KC] = t4;
    }
}

// ---------------- bisection (mirrors reference update rule) -----------------
__device__ __forceinline__ float calibrate(float a1, float a2, float a3, float a4,
                                           float target) {
    float mid0 = 0.f, mid1 = SIGMA_HI_V, sigma = 1.f;
#pragma unroll 1
    for (int it = 0; it < CAL_ITERS; it++) {
        float inv = __frcp_rn(sigma);
        float cur = 1.f + __expf(-a1 * inv) + __expf(-a2 * inv) +
                    __expf(-a3 * inv) + __expf(-a4 * inv);
        if (cur > target) mid1 = sigma; else mid0 = sigma;
        sigma = 0.5f * (mid0 + mid1);
    }
    return sigma;
}

// ---------------- K2: final column merge + sigma_u ---------------------------
__global__ void k_colfinal() {
    int col = blockIdx.x;
    int lane = threadIdx.x;  // 32 threads
    float t0 = INF_F, t1 = INF_F, t2 = INF_F, t3 = INF_F, t4 = INF_F;
    for (int b = lane; b < NPART; b += 32) {
        const float* pp = g_part1 + (size_t)b * 5 * KC + col;
#pragma unroll
        for (int s = 0; s < 5; s++) ins5(pp[s * KC], t0, t1, t2, t3, t4);
    }
#pragma unroll
    for (int off = 16; off; off >>= 1) {
        float o0 = __shfl_xor_sync(0xffffffffu, t0, off);
        float o1 = __shfl_xor_sync(0xffffffffu, t1, off);
        float o2 = __shfl_xor_sync(0xffffffffu, t2, off);
        float o3 = __shfl_xor_sync(0xffffffffu, t3, off);
        float o4 = __shfl_xor_sync(0xffffffffu, t4, off);
        ins5(o0, t0, t1, t2, t3, t4);
        ins5(o1, t0, t1, t2, t3, t4);
        ins5(o2, t0, t1, t2, t3, t4);
        ins5(o3, t0, t1, t2, t3, t4);
        ins5(o4, t0, t1, t2, t3, t4);
    }
    if (lane == 0) {
        float rho = t0;
        g_rhou[col] = rho;
        float a1 = fmaxf(t1 - rho, 0.f), a2 = fmaxf(t2 - rho, 0.f);
        float a3 = fmaxf(t3 - rho, 0.f), a4 = fmaxf(t4 - rho, 0.f);
        g_sigu[col] = calibrate(a1, a2, a3, a4, TARGET_U);
    }
}

// ---------------- K3: merge row halves + sigma_z ------------------------------
__global__ __launch_bounds__(256) void k_sigz() {
    int row = blockIdx.x * 256 + threadIdx.x;
    const float* p0 = g_rowp + (size_t)row * 5;
    const float* p1 = g_rowp + (size_t)NROWS * 5 + (size_t)row * 5;
    float t0 = INF_F, t1 = INF_F, t2 = INF_F, t3 = INF_F, t4 = INF_F;
#pragma unroll
    for (int s = 0; s < 5; s++) ins5(p0[s], t0, t1, t2, t3, t4);
#pragma unroll
    for (int s = 0; s < 5; s++) ins5(p1[s], t0, t1, t2, t3, t4);
    float rho = t0;
    g_rhoz[row] = rho;
    float a1 = fmaxf(t1 - rho, 0.f), a2 = fmaxf(t2 - rho, 0.f);
    float a3 = fmaxf(t3 - rho, 0.f), a4 = fmaxf(t4 - rho, 0.f);
    g_sigz[row] = calibrate(a1, a2, a3, a4, TARGET_Z);
}

// ---------------- K4: W1 / W2 / S + colsum (warp per row) -------------------
__global__ __launch_bounds__(256) void k_ws(float* __restrict__ out) {
    __shared__ float s_rho[KC], s_isu[KC], s_cs[KC];
    int t = threadIdx.x;
    s_rho[t] = g_rhou[t];
    s_isu[t] = 1.0f / g_sigu[t];
    s_cs[t] = 0.f;
    __syncthreads();

    int lane = t & 31;
    int wid = (blockIdx.x << 3) + (t >> 5);
    float* outW1a = out;
    float* outS   = out + NKSZ;
    float* outW1b = out + 2 * NKSZ;
    const int wstride = gridDim.x << 3;

    for (int row = wid; row < NROWS; row += wstride) {
        float rho = g_rhoz[row];
        float isz = 1.0f / g_sigz[row];
        const float* dr = g_d + (size_t)row * KC;
        float w1v[8], sv[8];
        float sum = 0.f;
#pragma unroll
        for (int i = 0; i < 8; i++) {
            int c = lane + (i << 5);
            float v = dr[c];
            float w1 = __expf(-fmaxf(v - rho, 0.f) * isz);
            float w2 = __expf(-fmaxf(v - s_rho[c], 0.f) * s_isu[c]);
            float s = w1 + w2 - w1 * w2;
            w1v[i] = w1; sv[i] = s; sum += s;
        }
#pragma unroll
        for (int off = 16; off; off >>= 1) sum += __shfl_xor_sync(0xffffffffu, sum, off);
        float rinv = 1.0f / sum;
#pragma unroll
        for (int i = 0; i < 8; i++) {
            int c = lane + (i << 5);
            size_t idx = (size_t)row * KC + c;
            float S = sv[i] * rinv;
            outW1a[idx] = w1v[i];
            outW1b[idx] = w1v[i];
            outS[idx] = S;
            atomicAdd(&s_cs[c], S);
        }
    }
    __syncthreads();
    atomicAdd(&g_colsum[t], s_cs[t]);
}

// ---------------- K5: Dmat ---------------------------------------------------
__global__ __launch_bounds__(256) void k_dmat(float* __restrict__ out) {
    __shared__ float s_ic[KC];
    int t = threadIdx.x;
    s_ic[t] = 1.0f / g_colsum[t];
    __syncthreads();

    const float* Sm = out + NKSZ;
    float* Dm = out + 3 * NKSZ;
    int lane = t & 31;
    int wid = (blockIdx.x << 3) + (t >> 5);
    const int wstride = gridDim.x << 3;

    for (int row = wid; row < NROWS; row += wstride) {
        const float* sr = Sm + (size_t)row * KC;
        float tv[8];
        float sum = 0.f;
#pragma unroll
        for (int i = 0; i < 8; i++) {
            int c = lane + (i << 5);
            float S = sr[c];
            float q = S * S * s_ic[c];
            tv[i] = q; sum += q;
        }
#pragma unroll
        for (int off = 16; off; off >>= 1) sum += __shfl_xor_sync(0xffffffffu, sum, off);
        float rinv = 1.0f / sum;
#pragma unroll
        for (int i = 0; i < 8; i++) {
            int c = lane + (i << 5);
            Dm[(size_t)row * KC + c] = tv[i] * rinv;
        }
    }
}

// ---------------- launcher ---------------------------------------------------
extern "C" void kernel_launch(void* const* d_in, const int* in_sizes, int n_in,
                              void* d_out, int out_size) {
    (void)in_sizes; (void)n_in; (void)out_size;
    const float* z  = (const float*)d_in[0];
    const float* mu = (const float*)d_in[1];
    float* out = (float*)d_out;

    cudaFuncSetAttribute(k_gemm, cudaFuncAttributeMaxDynamicSharedMemorySize,
                         GSMEM_TOTAL);

    k_prep_mu<<<1, 256>>>(mu);       // #1
    k_zero<<<1, 256>>>();            // #2
    k_noop<<<1, 32>>>();             // #3
    k_gemm<<<dim3(NROWS / 128, 2), 512, GSMEM_TOTAL>>>(z);   // #4 <- ncu slot
    k_colfinal<<<KC, 32>>>();        // #5
    k_sigz<<<NROWS / 256, 256>>>();  // #6
    k_ws<<<1024, 256>>>(out);        // #7
    k_dmat<<<1024, 256>>>(out);      // #8
}

// round 11
// speedup vs baseline: 1.4356x; 1.4356x over previous
#include <cuda_runtime.h>
#include <cuda_bf16.h>
#include <math.h>
#include <stdint.h>

#define NROWS 65536
#define KC 256
#define DH 256
#define NKSZ ((size_t)NROWS * KC)
#define EPSV 1e-6f
#define SIGMA_HI_V 10000.0f
#define TARGET_Z 1.3219281f   /* log2(5)-1 */
#define TARGET_U 2.3219281f   /* log2(5)   */
#define INF_F __int_as_float(0x7f800000)
#define CAL_ITERS 64
#define NPART 512

// ---------------- scratch (device globals; no runtime allocation) ----------
__device__ float g_d[NKSZ];                 // 64MB distance matrix
__device__ uint4 g_mhi4[KC * 64];           // mu hi tf32-in-f32 (16B quads)
__device__ uint4 g_mlo4[KC * 64];           // mu lo tf32-in-f32
__device__ float g_m2[KC], g_ms[KC];
__device__ float g_relz[(size_t)NROWS * 5];
__device__ float g_rhoz[NROWS];
__device__ float g_sigz[NROWS];
__device__ float g_part1[NPART * 5 * KC];   // [cta][s][col]
__device__ float g_rhou[KC];
__device__ float g_sigu[KC];
__device__ float g_colsum[KC];

// ---------------- PTX helpers (baseline PTX only) ----------------------------
__device__ __forceinline__ uint32_t smem_u32(const void* p) {
    uint32_t a;
    asm("{ .reg .u64 t; cvta.to.shared.u64 t, %1; cvt.u32.u64 %0, t; }" : "=r"(a) : "l"(p));
    return a;
}

__device__ __forceinline__ uint32_t tf32u(float x) {
    uint32_t u;
    asm("cvt.rna.tf32.f32 %0, %1;" : "=r"(u) : "f"(x));
    return u;
}

__device__ __forceinline__ void ldmx4(uint32_t* r, uint32_t addr) {
    asm volatile("ldmatrix.sync.aligned.m8n8.x4.shared.b16 {%0,%1,%2,%3}, [%4];"
                 : "=r"(r[0]), "=r"(r[1]), "=r"(r[2]), "=r"(r[3]) : "r"(addr));
}

__device__ __forceinline__ void mma_tf32(float* d, const uint32_t* a, const uint32_t* b) {
    asm volatile(
        "mma.sync.aligned.m16n8k8.row.col.f32.tf32.tf32.f32 "
        "{%0,%1,%2,%3}, {%4,%5,%6,%7}, {%8,%9}, {%0,%1,%2,%3};"
        : "+f"(d[0]), "+f"(d[1]), "+f"(d[2]), "+f"(d[3])
        : "r"(a[0]), "r"(a[1]), "r"(a[2]), "r"(a[3]), "r"(b[0]), "r"(b[1]));
}

// ---------------- K0: mu prep (hi/lo tf32 split + stats) ---------------------
__global__ void k_prep_mu(const float* __restrict__ mu) {
    int j = threadIdx.x;
    const float* r = mu + (size_t)j * DH;
    float m2 = 0.f, ms = 0.f;
    for (int i = 0; i < 64; i++) {
        float4 v = *(const float4*)(r + i * 4);
        float x[4] = {v.x, v.y, v.z, v.w};
        uint32_t hi[4], lo[4];
#pragma unroll
        for (int q = 0; q < 4; q++) {
            m2 = fmaf(x[q], x[q], m2);
            ms += x[q];
            hi[q] = tf32u(x[q]);
            lo[q] = tf32u(x[q] - __uint_as_float(hi[q]));
        }
        g_mhi4[j * 64 + i] = make_uint4(hi[0], hi[1], hi[2], hi[3]);
        g_mlo4[j * 64 + i] = make_uint4(lo[0], lo[1], lo[2], lo[3]);
    }
    g_m2[j] = m2;
    g_ms[j] = ms;
}

// ---------------- insertion helper ------------------------------------------
__device__ __forceinline__ void ins5(float v, float &t0, float &t1, float &t2,
                                     float &t3, float &t4) {
    if (v < t4) {
        if (v < t3) {
            t4 = t3;
            if (v < t2) {
                t3 = t2;
                if (v < t1) {
                    t2 = t1;
                    if (v < t0) { t1 = t0; t0 = v; } else t1 = v;
                } else t2 = v;
            } else t3 = v;
        } else t4 = v;
    }
}

// ---------------- K1: fused tf32-split GEMM + d + row/col top5 ---------------
// (byte-identical structure to R9 best: CTA 128x256, 16 warps, warp tile 32x64,
//  K in 4 chunks of 64, 3 passes hh+lh+hl, B streamed in pair groups)
#define LDS_A 68
#define TILE_LD 260
#define SA_HI 0
#define SA_LO 34816
#define SB_HI 69632
#define SB_LO 139264
#define ST_M2 208896
#define ST_MS 209920
#define ST_Z2 210944
#define ST_ZS 211456
#define GSMEM_TOTAL 211968

__global__ __launch_bounds__(512, 1) void k_gemm(const float* __restrict__ z) {
    extern __shared__ char smem[];
    const uint32_t sb = smem_u32(smem);
    const int t = threadIdx.x;
    const int wid = t >> 5, lane = t & 31;
    const int wr = wid >> 2, wc = wid & 3;
    const int rowBase = blockIdx.x * 128;

    float* s_m2 = (float*)(smem + ST_M2);
    float* s_ms = (float*)(smem + ST_MS);
    float* s_z2 = (float*)(smem + ST_Z2);
    float* s_zs = (float*)(smem + ST_ZS);
    if (t < 256) { s_m2[t] = g_m2[t]; s_ms[t] = g_ms[t]; }

    float acc[2][8][4];
#pragma unroll
    for (int mt = 0; mt < 2; mt++)
#pragma unroll
        for (int j = 0; j < 8; j++)
#pragma unroll
            for (int q = 0; q < 4; q++) acc[mt][j][q] = 0.f;

    const int ar = t >> 2, aq = t & 3;
    const float* zrow = z + (size_t)(rowBase + ar) * DH + aq * 16;
    float z2p = 0.f, zsp = 0.f;

    const uint32_t a_off = ((uint32_t)(wr * 32 + (lane & 15)) * LDS_A +
                            ((lane >> 4) << 2)) * 4;
    const uint32_t b_off = ((uint32_t)(wc * 64 + ((lane >> 4) << 3) + (lane & 7)) * LDS_A +
                            ((lane & 8) >> 1)) * 4;

#pragma unroll 1
    for (int c = 0; c < 4; c++) {
        __syncthreads();
        {
            const float4* src = (const float4*)(zrow + c * 64);
            uint32_t off = ((uint32_t)ar * LDS_A + aq * 16) * 4;
#pragma unroll
            for (int g = 0; g < 4; g++) {
                float4 v = src[g];
                z2p = fmaf(v.x, v.x, fmaf(v.y, v.y, fmaf(v.z, v.z, fmaf(v.w, v.w, z2p))));
                zsp += v.x + v.y + v.z + v.w;
                uint32_t hx = tf32u(v.x), hy = tf32u(v.y);
                uint32_t hz = tf32u(v.z), hw = tf32u(v.w);
                float4 hv = make_float4(__uint_as_float(hx), __uint_as_float(hy),
                                        __uint_as_float(hz), __uint_as_float(hw));
                float4 lv = make_float4(
                    __uint_as_float(tf32u(v.x - hv.x)), __uint_as_float(tf32u(v.y - hv.y)),
                    __uint_as_float(tf32u(v.z - hv.z)), __uint_as_float(tf32u(v.w - hv.w)));
                *(float4*)(smem + SA_HI + off + g * 16) = hv;
                *(float4*)(smem + SA_LO + off + g * 16) = lv;
            }
        }
#pragma unroll
        for (int i = 0; i < 8; i++) {
            int e = t + 512 * i;
            int row = e >> 4, q = e & 15;
            uint32_t off = ((uint32_t)row * LDS_A + q * 4) * 4;
            *(uint4*)(smem + SB_HI + off) = g_mhi4[row * 64 + c * 16 + q];
            *(uint4*)(smem + SB_LO + off) = g_mlo4[row * 64 + c * 16 + q];
        }
        __syncthreads();

#pragma unroll
        for (int ks = 0; ks < 8; ks++) {
            const uint32_t kb = (uint32_t)ks * 32;
            uint32_t ah[2][4], al[2][4];
            ldmx4(ah[0], sb + SA_HI + a_off + kb);
            ldmx4(ah[1], sb + SA_HI + a_off + kb + 16 * LDS_A * 4);
            ldmx4(al[0], sb + SA_LO + a_off + kb);
            ldmx4(al[1], sb + SA_LO + a_off + kb + 16 * LDS_A * 4);
#pragma unroll
            for (int pp = 0; pp < 2; pp++) {
                const int p0 = 2 * pp, p1 = 2 * pp + 1;
                const uint32_t pb0 = (uint32_t)p0 * 16 * LDS_A * 4;
                const uint32_t pb1 = (uint32_t)p1 * 16 * LDS_A * 4;
                uint32_t bh0[4], bh1[4];
                ldmx4(bh0, sb + SB_HI + b_off + kb + pb0);
                ldmx4(bh1, sb + SB_HI + b_off + kb + pb1);
                mma_tf32(acc[0][2 * p0],     ah[0], &bh0[0]);
                mma_tf32(acc[0][2 * p0 + 1], ah[0], &bh0[2]);
                mma_tf32(acc[1][2 * p0],     ah[1], &bh0[0]);
                mma_tf32(acc[1][2 * p0 + 1], ah[1], &bh0[2]);
                mma_tf32(acc[0][2 * p1],     ah[0], &bh1[0]);
                mma_tf32(acc[0][2 * p1 + 1], ah[0], &bh1[2]);
                mma_tf32(acc[1][2 * p1],     ah[1], &bh1[0]);
                mma_tf32(acc[1][2 * p1 + 1], ah[1], &bh1[2]);
                uint32_t bl0[4], bl1[4];
                ldmx4(bl0, sb + SB_LO + b_off + kb + pb0);
                ldmx4(bl1, sb + SB_LO + b_off + kb + pb1);
                mma_tf32(acc[0][2 * p0],     al[0], &bh0[0]);
                mma_tf32(acc[0][2 * p0 + 1], al[0], &bh0[2]);
                mma_tf32(acc[1][2 * p0],     al[1], &bh0[0]);
                mma_tf32(acc[1][2 * p0 + 1], al[1], &bh0[2]);
                mma_tf32(acc[0][2 * p1],     al[0], &bh1[0]);
                mma_tf32(acc[0][2 * p1 + 1], al[0], &bh1[2]);
                mma_tf32(acc[1][2 * p1],     al[1], &bh1[0]);
                mma_tf32(acc[1][2 * p1 + 1], al[1], &bh1[2]);
                mma_tf32(acc[0][2 * p0],     ah[0], &bl0[0]);
                mma_tf32(acc[0][2 * p0 + 1], ah[0], &bl0[2]);
                mma_tf32(acc[1][2 * p0],     ah[1], &bl0[0]);
                mma_tf32(acc[1][2 * p0 + 1], ah[1], &bl0[2]);
                mma_tf32(acc[0][2 * p1],     ah[0], &bl1[0]);
                mma_tf32(acc[0][2 * p1 + 1], ah[0], &bl1[2]);
                mma_tf32(acc[1][2 * p1],     ah[1], &bl1[0]);
                mma_tf32(acc[1][2 * p1 + 1], ah[1], &bl1[2]);
            }
        }
    }

    z2p += __shfl_xor_sync(0xffffffffu, z2p, 1);
    z2p += __shfl_xor_sync(0xffffffffu, z2p, 2);
    zsp += __shfl_xor_sync(0xffffffffu, zsp, 1);
    zsp += __shfl_xor_sync(0xffffffffu, zsp, 2);
    if (aq == 0) { s_z2[ar] = z2p; s_zs[ar] = zsp; }
    __syncthreads();

    float* tile = (float*)smem;
    const float cterm = (float)DH * EPSV * EPSV;
#pragma unroll
    for (int mt = 0; mt < 2; mt++) {
        const int r0 = wr * 32 + mt * 16 + (lane >> 2);
        const float z2va = s_z2[r0], zsva = s_zs[r0];
        const float z2vb = s_z2[r0 + 8], zsvb = s_zs[r0 + 8];
#pragma unroll
        for (int nt = 0; nt < 8; nt++) {
            const int c0 = wc * 64 + nt * 8 + (lane & 3) * 2;
            float m20 = s_m2[c0], ms0 = s_ms[c0];
            float m21 = s_m2[c0 + 1], ms1 = s_ms[c0 + 1];
            float d00 = z2va + m20 - 2.f * acc[mt][nt][0] + 2.f * EPSV * (zsva - ms0) + cterm;
            float d01 = z2va + m21 - 2.f * acc[mt][nt][1] + 2.f * EPSV * (zsva - ms1) + cterm;
            float d10 = z2vb + m20 - 2.f * acc[mt][nt][2] + 2.f * EPSV * (zsvb - ms0) + cterm;
            float d11 = z2vb + m21 - 2.f * acc[mt][nt][3] + 2.f * EPSV * (zsvb - ms1) + cterm;
            tile[r0 * TILE_LD + c0]           = sqrtf(fmaxf(d00, 0.f));
            tile[r0 * TILE_LD + c0 + 1]       = sqrtf(fmaxf(d01, 0.f));
            tile[(r0 + 8) * TILE_LD + c0]     = sqrtf(fmaxf(d10, 0.f));
            tile[(r0 + 8) * TILE_LD + c0 + 1] = sqrtf(fmaxf(d11, 0.f));
        }
    }
    __syncthreads();

#pragma unroll
    for (int i = 0; i < 16; i++) {
        int e = t + 512 * i;
        int row = e >> 6, c4 = e & 63;
        float4 v = *(const float4*)&tile[row * TILE_LD + c4 * 4];
        *(float4*)&g_d[(size_t)(rowBase + row) * KC + c4 * 4] = v;
    }

#pragma unroll 1
    for (int rr = 0; rr < 8; rr++) {
        int lrow = wid * 8 + rr;
        float t0 = INF_F, t1 = INF_F, t2 = INF_F, t3 = INF_F, t4 = INF_F;
#pragma unroll
        for (int i = 0; i < 8; i++)
            ins5(tile[lrow * TILE_LD + lane + 32 * i], t0, t1, t2, t3, t4);
#pragma unroll
        for (int off = 16; off; off >>= 1) {
            float o0 = __shfl_xor_sync(0xffffffffu, t0, off);
            float o1 = __shfl_xor_sync(0xffffffffu, t1, off);
            float o2 = __shfl_xor_sync(0xffffffffu, t2, off);
            float o3 = __shfl_xor_sync(0xffffffffu, t3, off);
            float o4 = __shfl_xor_sync(0xffffffffu, t4, off);
            ins5(o0, t0, t1, t2, t3, t4);
            ins5(o1, t0, t1, t2, t3, t4);
            ins5(o2, t0, t1, t2, t3, t4);
            ins5(o3, t0, t1, t2, t3, t4);
            ins5(o4, t0, t1, t2, t3, t4);
        }
        if (lane == 0) {
            int grow = rowBase + lrow;
            g_rhoz[grow] = t0;
            float* rp = g_relz + (size_t)grow * 5;
            rp[0] = t0; rp[1] = t1; rp[2] = t2; rp[3] = t3; rp[4] = t4;
        }
    }

    if (t < 256) {
        float t0 = INF_F, t1 = INF_F, t2 = INF_F, t3 = INF_F, t4 = INF_F;
#pragma unroll 4
        for (int r = 0; r < 128; r++)
            ins5(tile[r * TILE_LD + t], t0, t1, t2, t3, t4);
        float* pp = g_part1 + (size_t)blockIdx.x * 5 * KC + t;
        pp[0 * KC] = t0; pp[1 * KC] = t1; pp[2 * KC] = t2;
        pp[3 * KC] = t3; pp[4 * KC] = t4;
    }
}

// ---------------- bisection (mirrors reference update rule) -----------------
__device__ __forceinline__ float calibrate(float a1, float a2, float a3, float a4,
                                           float target) {
    float mid0 = 0.f, mid1 = SIGMA_HI_V, sigma = 1.f;
#pragma unroll 1
    for (int it = 0; it < CAL_ITERS; it++) {
        float inv = __frcp_rn(sigma);
        float cur = 1.f + __expf(-a1 * inv) + __expf(-a2 * inv) +
                    __expf(-a3 * inv) + __expf(-a4 * inv);
        if (cur > target) mid1 = sigma; else mid0 = sigma;
        sigma = 0.5f * (mid0 + mid1);
    }
    return sigma;
}

// ---------------- K2: fused reductions ---------------------------------------
// blocks 0..31  : column top5 merge + sigma_u + colsum zero (warp per column)
// blocks 32..287: sigma_z (thread per row)
__global__ __launch_bounds__(256) void k_reduce() {
    int b = blockIdx.x;
    if (b < 32) {
        int w = threadIdx.x >> 5, lane = threadIdx.x & 31;
        int col = b * 8 + w;
        float t0 = INF_F, t1 = INF_F, t2 = INF_F, t3 = INF_F, t4 = INF_F;
        for (int p = lane; p < NPART; p += 32) {
            const float* pp = g_part1 + (size_t)p * 5 * KC + col;
#pragma unroll
            for (int s = 0; s < 5; s++) ins5(pp[s * KC], t0, t1, t2, t3, t4);
        }
#pragma unroll
        for (int off = 16; off; off >>= 1) {
            float o0 = __shfl_xor_sync(0xffffffffu, t0, off);
            float o1 = __shfl_xor_sync(0xffffffffu, t1, off);
            float o2 = __shfl_xor_sync(0xffffffffu, t2, off);
            float o3 = __shfl_xor_sync(0xffffffffu, t3, off);
            float o4 = __shfl_xor_sync(0xffffffffu, t4, off);
            ins5(o0, t0, t1, t2, t3, t4);
            ins5(o1, t0, t1, t2, t3, t4);
            ins5(o2, t0, t1, t2, t3, t4);
            ins5(o3, t0, t1, t2, t3, t4);
            ins5(o4, t0, t1, t2, t3, t4);
        }
        if (lane == 0) {
            float rho = t0;
            g_rhou[col] = rho;
            g_colsum[col] = 0.f;
            float a1 = fmaxf(t1 - rho, 0.f), a2 = fmaxf(t2 - rho, 0.f);
            float a3 = fmaxf(t3 - rho, 0.f), a4 = fmaxf(t4 - rho, 0.f);
            g_sigu[col] = calibrate(a1, a2, a3, a4, TARGET_U);
        }
    } else {
        int row = (b - 32) * 256 + threadIdx.x;
        const float* r = g_relz + (size_t)row * 5;
        float rho = r[0];
        float a1 = fmaxf(r[1] - rho, 0.f), a2 = fmaxf(r[2] - rho, 0.f);
        float a3 = fmaxf(r[3] - rho, 0.f), a4 = fmaxf(r[4] - rho, 0.f);
        g_rhoz[row] = rho;
        g_sigz[row] = calibrate(a1, a2, a3, a4, TARGET_Z);
    }
}

// ---------------- K3: W1 / W2 / S + colsum (warp per row, float4 I/O) --------
__global__ __launch_bounds__(256) void k_ws(float* __restrict__ out) {
    __shared__ float s_rho[KC], s_isu[KC], s_cs[KC];
    int t = threadIdx.x;
    s_rho[t] = g_rhou[t];
    s_isu[t] = 1.0f / g_sigu[t];
    s_cs[t] = 0.f;
    __syncthreads();

    int lane = t & 31;
    int w = t >> 5;
    int wid = (blockIdx.x << 3) + w;
    const int c0 = lane * 4, c1 = 128 + lane * 4;
    float* outW1a = out;
    float* outS   = out + NKSZ;
    float* outW1b = out + 2 * NKSZ;

    // hoist per-lane column constants into registers
    float ru[8], iu[8];
#pragma unroll
    for (int j = 0; j < 4; j++) {
        ru[j] = s_rho[c0 + j];     iu[j] = s_isu[c0 + j];
        ru[4 + j] = s_rho[c1 + j]; iu[4 + j] = s_isu[c1 + j];
    }
    float cs[8];
#pragma unroll
    for (int j = 0; j < 8; j++) cs[j] = 0.f;

    for (int row = wid; row < NROWS; row += 8192) {
        float rho = g_rhoz[row];
        float isz = 1.0f / g_sigz[row];
        const float* dr = g_d + (size_t)row * KC;
        float4 d0 = *(const float4*)(dr + c0);
        float4 d1 = *(const float4*)(dr + c1);
        float dv[8] = {d0.x, d0.y, d0.z, d0.w, d1.x, d1.y, d1.z, d1.w};
        float w1v[8], sv[8];
        float sum = 0.f;
#pragma unroll
        for (int j = 0; j < 8; j++) {
            float w1 = __expf(-fmaxf(dv[j] - rho, 0.f) * isz);
            float w2 = __expf(-fmaxf(dv[j] - ru[j], 0.f) * iu[j]);
            float s = w1 + w2 - w1 * w2;
            w1v[j] = w1; sv[j] = s; sum += s;
        }
#pragma unroll
        for (int off = 16; off; off >>= 1) sum += __shfl_xor_sync(0xffffffffu, sum, off);
        float rinv = 1.0f / sum;
        float4 w1a = make_float4(w1v[0], w1v[1], w1v[2], w1v[3]);
        float4 w1b = make_float4(w1v[4], w1v[5], w1v[6], w1v[7]);
        float4 s0 = make_float4(sv[0] * rinv, sv[1] * rinv, sv[2] * rinv, sv[3] * rinv);
        float4 s1 = make_float4(sv[4] * rinv, sv[5] * rinv, sv[6] * rinv, sv[7] * rinv);
        size_t base = (size_t)row * KC;
        *(float4*)(outW1a + base + c0) = w1a;
        *(float4*)(outW1a + base + c1) = w1b;
        *(float4*)(outW1b + base + c0) = w1a;
        *(float4*)(outW1b + base + c1) = w1b;
        *(float4*)(outS + base + c0) = s0;
        *(float4*)(outS + base + c1) = s1;
        cs[0] += s0.x; cs[1] += s0.y; cs[2] += s0.z; cs[3] += s0.w;
        cs[4] += s1.x; cs[5] += s1.y; cs[6] += s1.z; cs[7] += s1.w;
    }
#pragma unroll
    for (int j = 0; j < 4; j++) {
        atomicAdd(&s_cs[c0 + j], cs[j]);
        atomicAdd(&s_cs[c1 + j], cs[4 + j]);
    }
    __syncthreads();
    atomicAdd(&g_colsum[t], s_cs[t]);
}

// ---------------- K4: Dmat (float4 I/O) ---------------------------------------
__global__ __launch_bounds__(256) void k_dmat(float* __restrict__ out) {
    __shared__ float s_ic[KC];
    int t = threadIdx.x;
    s_ic[t] = 1.0f / g_colsum[t];
    __syncthreads();

    const float* Sm = out + NKSZ;
    float* Dm = out + 3 * NKSZ;
    int lane = t & 31;
    int w = t >> 5;
    int wid = (blockIdx.x << 3) + w;
    const int c0 = lane * 4, c1 = 128 + lane * 4;

    float ic[8];
#pragma unroll
    for (int j = 0; j < 4; j++) {
        ic[j] = s_ic[c0 + j];
        ic[4 + j] = s_ic[c1 + j];
    }

    for (int row = wid; row < NROWS; row += 8192) {
        const float* sr = Sm + (size_t)row * KC;
        float4 v0 = *(const float4*)(sr + c0);
        float4 v1 = *(const float4*)(sr + c1);
        float sv[8] = {v0.x, v0.y, v0.z, v0.w, v1.x, v1.y, v1.z, v1.w};
        float tv[8];
        float sum = 0.f;
#pragma unroll
        for (int j = 0; j < 8; j++) {
            float q = sv[j] * sv[j] * ic[j];
            tv[j] = q; sum += q;
        }
#pragma unroll
        for (int off = 16; off; off >>= 1) sum += __shfl_xor_sync(0xffffffffu, sum, off);
        float rinv = 1.0f / sum;
        float4 o0 = make_float4(tv[0] * rinv, tv[1] * rinv, tv[2] * rinv, tv[3] * rinv);
        float4 o1 = make_float4(tv[4] * rinv, tv[5] * rinv, tv[6] * rinv, tv[7] * rinv);
        size_t base = (size_t)row * KC;
        *(float4*)(Dm + base + c0) = o0;
        *(float4*)(Dm + base + c1) = o1;
    }
}

// ---------------- launcher ---------------------------------------------------
extern "C" void kernel_launch(void* const* d_in, const int* in_sizes, int n_in,
                              void* d_out, int out_size) {
    (void)in_sizes; (void)n_in; (void)out_size;
    const float* z  = (const float*)d_in[0];
    const float* mu = (const float*)d_in[1];
    float* out = (float*)d_out;

    cudaFuncSetAttribute(k_gemm, cudaFuncAttributeMaxDynamicSharedMemorySize,
                         GSMEM_TOTAL);

    k_prep_mu<<<1, 256>>>(mu);                       // #1
    k_gemm<<<NROWS / 128, 512, GSMEM_TOTAL>>>(z);    // #2
    k_reduce<<<288, 256>>>();                        // #3
    k_ws<<<1024, 256>>>(out);                        // #4 <- ncu slot
    k_dmat<<<1024, 256>>>(out);                      // #5
}

// round 12
// speedup vs baseline: 1.5322x; 1.0673x over previous
#include <cuda_runtime.h>
#include <cuda_bf16.h>
#include <math.h>
#include <stdint.h>

#define NROWS 65536
#define KC 256
#define DH 256
#define NKSZ ((size_t)NROWS * KC)
#define EPSV 1e-6f
#define SIGMA_HI_V 10000.0f
#define TARGET_Z 1.3219281f   /* log2(5)-1 */
#define TARGET_U 2.3219281f   /* log2(5)   */
#define INF_F __int_as_float(0x7f800000)
#define CAL_ITERS 64
#define NPART 512

// ---------------- scratch (device globals; no runtime allocation) ----------
__device__ float g_d[NKSZ];                 // 64MB distance matrix
__device__ uint4 g_mhi4[KC * 64];           // mu hi tf32-in-f32 (16B quads)
__device__ uint4 g_mlo4[KC * 64];           // mu lo tf32-in-f32
__device__ float g_m2[KC], g_ms[KC];
__device__ float g_relz[(size_t)NROWS * 5];
__device__ float g_rhoz[NROWS];
__device__ float g_sigz[NROWS];
__device__ float g_part1[NPART * 5 * KC];   // [cta][s][col]
__device__ float g_rhou[KC];
__device__ float g_sigu[KC];
__device__ float g_colsum[KC];

// ---------------- PTX helpers (baseline PTX only) ----------------------------
__device__ __forceinline__ uint32_t smem_u32(const void* p) {
    uint32_t a;
    asm("{ .reg .u64 t; cvta.to.shared.u64 t, %1; cvt.u32.u64 %0, t; }" : "=r"(a) : "l"(p));
    return a;
}

__device__ __forceinline__ uint32_t tf32u(float x) {
    uint32_t u;
    asm("cvt.rna.tf32.f32 %0, %1;" : "=r"(u) : "f"(x));
    return u;
}

__device__ __forceinline__ void ldmx4(uint32_t* r, uint32_t addr) {
    asm volatile("ldmatrix.sync.aligned.m8n8.x4.shared.b16 {%0,%1,%2,%3}, [%4];"
                 : "=r"(r[0]), "=r"(r[1]), "=r"(r[2]), "=r"(r[3]) : "r"(addr));
}

__device__ __forceinline__ void mma_tf32(float* d, const uint32_t* a, const uint32_t* b) {
    asm volatile(
        "mma.sync.aligned.m16n8k8.row.col.f32.tf32.tf32.f32 "
        "{%0,%1,%2,%3}, {%4,%5,%6,%7}, {%8,%9}, {%0,%1,%2,%3};"
        : "+f"(d[0]), "+f"(d[1]), "+f"(d[2]), "+f"(d[3])
        : "r"(a[0]), "r"(a[1]), "r"(a[2]), "r"(a[3]), "r"(b[0]), "r"(b[1]));
}

// ---------------- K0: mu prep (warp per row; parallel) ------------------------
__global__ __launch_bounds__(256) void k_prep_mu(const float* __restrict__ mu) {
    int row = blockIdx.x * 8 + (threadIdx.x >> 5);
    int lane = threadIdx.x & 31;
    // lane handles elements 8*lane .. 8*lane+7 (2 quads)
    const float* r = mu + (size_t)row * DH + lane * 8;
    float m2 = 0.f, ms = 0.f;
#pragma unroll
    for (int g = 0; g < 2; g++) {
        float4 v = *(const float4*)(r + g * 4);
        float x[4] = {v.x, v.y, v.z, v.w};
        uint32_t hi[4], lo[4];
#pragma unroll
        for (int q = 0; q < 4; q++) {
            m2 = fmaf(x[q], x[q], m2);
            ms += x[q];
            hi[q] = tf32u(x[q]);
            lo[q] = tf32u(x[q] - __uint_as_float(hi[q]));
        }
        g_mhi4[row * 64 + lane * 2 + g] = make_uint4(hi[0], hi[1], hi[2], hi[3]);
        g_mlo4[row * 64 + lane * 2 + g] = make_uint4(lo[0], lo[1], lo[2], lo[3]);
    }
#pragma unroll
    for (int off = 16; off; off >>= 1) {
        m2 += __shfl_xor_sync(0xffffffffu, m2, off);
        ms += __shfl_xor_sync(0xffffffffu, ms, off);
    }
    if (lane == 0) { g_m2[row] = m2; g_ms[row] = ms; }
}

// ---------------- insertion helper ------------------------------------------
__device__ __forceinline__ void ins5(float v, float &t0, float &t1, float &t2,
                                     float &t3, float &t4) {
    if (v < t4) {
        if (v < t3) {
            t4 = t3;
            if (v < t2) {
                t3 = t2;
                if (v < t1) {
                    t2 = t1;
                    if (v < t0) { t1 = t0; t0 = v; } else t1 = v;
                } else t2 = v;
            } else t3 = v;
        } else t4 = v;
    }
}

// ---------------- K1: fused tf32-split GEMM + d + row/col top5 ---------------
// (byte-identical structure to R11 best)
#define LDS_A 68
#define TILE_LD 260
#define SA_HI 0
#define SA_LO 34816
#define SB_HI 69632
#define SB_LO 139264
#define ST_M2 208896
#define ST_MS 209920
#define ST_Z2 210944
#define ST_ZS 211456
#define GSMEM_TOTAL 211968

__global__ __launch_bounds__(512, 1) void k_gemm(const float* __restrict__ z) {
    extern __shared__ char smem[];
    const uint32_t sb = smem_u32(smem);
    const int t = threadIdx.x;
    const int wid = t >> 5, lane = t & 31;
    const int wr = wid >> 2, wc = wid & 3;
    const int rowBase = blockIdx.x * 128;

    float* s_m2 = (float*)(smem + ST_M2);
    float* s_ms = (float*)(smem + ST_MS);
    float* s_z2 = (float*)(smem + ST_Z2);
    float* s_zs = (float*)(smem + ST_ZS);
    if (t < 256) { s_m2[t] = g_m2[t]; s_ms[t] = g_ms[t]; }

    float acc[2][8][4];
#pragma unroll
    for (int mt = 0; mt < 2; mt++)
#pragma unroll
        for (int j = 0; j < 8; j++)
#pragma unroll
            for (int q = 0; q < 4; q++) acc[mt][j][q] = 0.f;

    const int ar = t >> 2, aq = t & 3;
    const float* zrow = z + (size_t)(rowBase + ar) * DH + aq * 16;
    float z2p = 0.f, zsp = 0.f;

    const uint32_t a_off = ((uint32_t)(wr * 32 + (lane & 15)) * LDS_A +
                            ((lane >> 4) << 2)) * 4;
    const uint32_t b_off = ((uint32_t)(wc * 64 + ((lane >> 4) << 3) + (lane & 7)) * LDS_A +
                            ((lane & 8) >> 1)) * 4;

#pragma unroll 1
    for (int c = 0; c < 4; c++) {
        __syncthreads();
        {
            const float4* src = (const float4*)(zrow + c * 64);
            uint32_t off = ((uint32_t)ar * LDS_A + aq * 16) * 4;
#pragma unroll
            for (int g = 0; g < 4; g++) {
                float4 v = src[g];
                z2p = fmaf(v.x, v.x, fmaf(v.y, v.y, fmaf(v.z, v.z, fmaf(v.w, v.w, z2p))));
                zsp += v.x + v.y + v.z + v.w;
                uint32_t hx = tf32u(v.x), hy = tf32u(v.y);
                uint32_t hz = tf32u(v.z), hw = tf32u(v.w);
                float4 hv = make_float4(__uint_as_float(hx), __uint_as_float(hy),
                                        __uint_as_float(hz), __uint_as_float(hw));
                float4 lv = make_float4(
                    __uint_as_float(tf32u(v.x - hv.x)), __uint_as_float(tf32u(v.y - hv.y)),
                    __uint_as_float(tf32u(v.z - hv.z)), __uint_as_float(tf32u(v.w - hv.w)));
                *(float4*)(smem + SA_HI + off + g * 16) = hv;
                *(float4*)(smem + SA_LO + off + g * 16) = lv;
            }
        }
#pragma unroll
        for (int i = 0; i < 8; i++) {
            int e = t + 512 * i;
            int row = e >> 4, q = e & 15;
            uint32_t off = ((uint32_t)row * LDS_A + q * 4) * 4;
            *(uint4*)(smem + SB_HI + off) = g_mhi4[row * 64 + c * 16 + q];
            *(uint4*)(smem + SB_LO + off) = g_mlo4[row * 64 + c * 16 + q];
        }
        __syncthreads();

#pragma unroll
        for (int ks = 0; ks < 8; ks++) {
            const uint32_t kb = (uint32_t)ks * 32;
            uint32_t ah[2][4], al[2][4];
            ldmx4(ah[0], sb + SA_HI + a_off + kb);
            ldmx4(ah[1], sb + SA_HI + a_off + kb + 16 * LDS_A * 4);
            ldmx4(al[0], sb + SA_LO + a_off + kb);
            ldmx4(al[1], sb + SA_LO + a_off + kb + 16 * LDS_A * 4);
#pragma unroll
            for (int pp = 0; pp < 2; pp++) {
                const int p0 = 2 * pp, p1 = 2 * pp + 1;
                const uint32_t pb0 = (uint32_t)p0 * 16 * LDS_A * 4;
                const uint32_t pb1 = (uint32_t)p1 * 16 * LDS_A * 4;
                uint32_t bh0[4], bh1[4];
                ldmx4(bh0, sb + SB_HI + b_off + kb + pb0);
                ldmx4(bh1, sb + SB_HI + b_off + kb + pb1);
                mma_tf32(acc[0][2 * p0],     ah[0], &bh0[0]);
                mma_tf32(acc[0][2 * p0 + 1], ah[0], &bh0[2]);
                mma_tf32(acc[1][2 * p0],     ah[1], &bh0[0]);
                mma_tf32(acc[1][2 * p0 + 1], ah[1], &bh0[2]);
                mma_tf32(acc[0][2 * p1],     ah[0], &bh1[0]);
                mma_tf32(acc[0][2 * p1 + 1], ah[0], &bh1[2]);
                mma_tf32(acc[1][2 * p1],     ah[1], &bh1[0]);
                mma_tf32(acc[1][2 * p1 + 1], ah[1], &bh1[2]);
                uint32_t bl0[4], bl1[4];
                ldmx4(bl0, sb + SB_LO + b_off + kb + pb0);
                ldmx4(bl1, sb + SB_LO + b_off + kb + pb1);
                mma_tf32(acc[0][2 * p0],     al[0], &bh0[0]);
                mma_tf32(acc[0][2 * p0 + 1], al[0], &bh0[2]);
                mma_tf32(acc[1][2 * p0],     al[1], &bh0[0]);
                mma_tf32(acc[1][2 * p0 + 1], al[1], &bh0[2]);
                mma_tf32(acc[0][2 * p1],     al[0], &bh1[0]);
                mma_tf32(acc[0][2 * p1 + 1], al[0], &bh1[2]);
                mma_tf32(acc[1][2 * p1],     al[1], &bh1[0]);
                mma_tf32(acc[1][2 * p1 + 1], al[1], &bh1[2]);
                mma_tf32(acc[0][2 * p0],     ah[0], &bl0[0]);
                mma_tf32(acc[0][2 * p0 + 1], ah[0], &bl0[2]);
                mma_tf32(acc[1][2 * p0],     ah[1], &bl0[0]);
                mma_tf32(acc[1][2 * p0 + 1], ah[1], &bl0[2]);
                mma_tf32(acc[0][2 * p1],     ah[0], &bl1[0]);
                mma_tf32(acc[0][2 * p1 + 1], ah[0], &bl1[2]);
                mma_tf32(acc[1][2 * p1],     ah[1], &bl1[0]);
                mma_tf32(acc[1][2 * p1 + 1], ah[1], &bl1[2]);
            }
        }
    }

    z2p += __shfl_xor_sync(0xffffffffu, z2p, 1);
    z2p += __shfl_xor_sync(0xffffffffu, z2p, 2);
    zsp += __shfl_xor_sync(0xffffffffu, zsp, 1);
    zsp += __shfl_xor_sync(0xffffffffu, zsp, 2);
    if (aq == 0) { s_z2[ar] = z2p; s_zs[ar] = zsp; }
    __syncthreads();

    float* tile = (float*)smem;
    const float cterm = (float)DH * EPSV * EPSV;
#pragma unroll
    for (int mt = 0; mt < 2; mt++) {
        const int r0 = wr * 32 + mt * 16 + (lane >> 2);
        const float z2va = s_z2[r0], zsva = s_zs[r0];
        const float z2vb = s_z2[r0 + 8], zsvb = s_zs[r0 + 8];
#pragma unroll
        for (int nt = 0; nt < 8; nt++) {
            const int c0 = wc * 64 + nt * 8 + (lane & 3) * 2;
            float m20 = s_m2[c0], ms0 = s_ms[c0];
            float m21 = s_m2[c0 + 1], ms1 = s_ms[c0 + 1];
            float d00 = z2va + m20 - 2.f * acc[mt][nt][0] + 2.f * EPSV * (zsva - ms0) + cterm;
            float d01 = z2va + m21 - 2.f * acc[mt][nt][1] + 2.f * EPSV * (zsva - ms1) + cterm;
            float d10 = z2vb + m20 - 2.f * acc[mt][nt][2] + 2.f * EPSV * (zsvb - ms0) + cterm;
            float d11 = z2vb + m21 - 2.f * acc[mt][nt][3] + 2.f * EPSV * (zsvb - ms1) + cterm;
            tile[r0 * TILE_LD + c0]           = sqrtf(fmaxf(d00, 0.f));
            tile[r0 * TILE_LD + c0 + 1]       = sqrtf(fmaxf(d01, 0.f));
            tile[(r0 + 8) * TILE_LD + c0]     = sqrtf(fmaxf(d10, 0.f));
            tile[(r0 + 8) * TILE_LD + c0 + 1] = sqrtf(fmaxf(d11, 0.f));
        }
    }
    __syncthreads();

#pragma unroll
    for (int i = 0; i < 16; i++) {
        int e = t + 512 * i;
        int row = e >> 6, c4 = e & 63;
        float4 v = *(const float4*)&tile[row * TILE_LD + c4 * 4];
        *(float4*)&g_d[(size_t)(rowBase + row) * KC + c4 * 4] = v;
    }

#pragma unroll 1
    for (int rr = 0; rr < 8; rr++) {
        int lrow = wid * 8 + rr;
        float t0 = INF_F, t1 = INF_F, t2 = INF_F, t3 = INF_F, t4 = INF_F;
#pragma unroll
        for (int i = 0; i < 8; i++)
            ins5(tile[lrow * TILE_LD + lane + 32 * i], t0, t1, t2, t3, t4);
#pragma unroll
        for (int off = 16; off; off >>= 1) {
            float o0 = __shfl_xor_sync(0xffffffffu, t0, off);
            float o1 = __shfl_xor_sync(0xffffffffu, t1, off);
            float o2 = __shfl_xor_sync(0xffffffffu, t2, off);
            float o3 = __shfl_xor_sync(0xffffffffu, t3, off);
            float o4 = __shfl_xor_sync(0xffffffffu, t4, off);
            ins5(o0, t0, t1, t2, t3, t4);
            ins5(o1, t0, t1, t2, t3, t4);
            ins5(o2, t0, t1, t2, t3, t4);
            ins5(o3, t0, t1, t2, t3, t4);
            ins5(o4, t0, t1, t2, t3, t4);
        }
        if (lane == 0) {
            int grow = rowBase + lrow;
            g_rhoz[grow] = t0;
            float* rp = g_relz + (size_t)grow * 5;
            rp[0] = t0; rp[1] = t1; rp[2] = t2; rp[3] = t3; rp[4] = t4;
        }
    }

    if (t < 256) {
        float t0 = INF_F, t1 = INF_F, t2 = INF_F, t3 = INF_F, t4 = INF_F;
#pragma unroll 4
        for (int r = 0; r < 128; r++)
            ins5(tile[r * TILE_LD + t], t0, t1, t2, t3, t4);
        float* pp = g_part1 + (size_t)blockIdx.x * 5 * KC + t;
        pp[0 * KC] = t0; pp[1 * KC] = t1; pp[2 * KC] = t2;
        pp[3 * KC] = t3; pp[4 * KC] = t4;
    }
}

// ---------------- bisection (mirrors reference update rule) -----------------
__device__ __forceinline__ float calibrate(float a1, float a2, float a3, float a4,
                                           float target) {
    float mid0 = 0.f, mid1 = SIGMA_HI_V, sigma = 1.f;
#pragma unroll 1
    for (int it = 0; it < CAL_ITERS; it++) {
        float inv = __frcp_rn(sigma);
        float cur = 1.f + __expf(-a1 * inv) + __expf(-a2 * inv) +
                    __expf(-a3 * inv) + __expf(-a4 * inv);
        if (cur > target) mid1 = sigma; else mid0 = sigma;
        sigma = 0.5f * (mid0 + mid1);
    }
    return sigma;
}

// ---------------- K2: fused reductions ---------------------------------------
__global__ __launch_bounds__(256) void k_reduce() {
    int b = blockIdx.x;
    if (b < 32) {
        int w = threadIdx.x >> 5, lane = threadIdx.x & 31;
        int col = b * 8 + w;
        float t0 = INF_F, t1 = INF_F, t2 = INF_F, t3 = INF_F, t4 = INF_F;
        for (int p = lane; p < NPART; p += 32) {
            const float* pp = g_part1 + (size_t)p * 5 * KC + col;
#pragma unroll
            for (int s = 0; s < 5; s++) ins5(pp[s * KC], t0, t1, t2, t3, t4);
        }
#pragma unroll
        for (int off = 16; off; off >>= 1) {
            float o0 = __shfl_xor_sync(0xffffffffu, t0, off);
            float o1 = __shfl_xor_sync(0xffffffffu, t1, off);
            float o2 = __shfl_xor_sync(0xffffffffu, t2, off);
            float o3 = __shfl_xor_sync(0xffffffffu, t3, off);
            float o4 = __shfl_xor_sync(0xffffffffu, t4, off);
            ins5(o0, t0, t1, t2, t3, t4);
            ins5(o1, t0, t1, t2, t3, t4);
            ins5(o2, t0, t1, t2, t3, t4);
            ins5(o3, t0, t1, t2, t3, t4);
            ins5(o4, t0, t1, t2, t3, t4);
        }
        if (lane == 0) {
            float rho = t0;
            g_rhou[col] = rho;
            g_colsum[col] = 0.f;
            float a1 = fmaxf(t1 - rho, 0.f), a2 = fmaxf(t2 - rho, 0.f);
            float a3 = fmaxf(t3 - rho, 0.f), a4 = fmaxf(t4 - rho, 0.f);
            g_sigu[col] = calibrate(a1, a2, a3, a4, TARGET_U);
        }
    } else {
        int row = (b - 32) * 256 + threadIdx.x;
        const float* r = g_relz + (size_t)row * 5;
        float rho = r[0];
        float a1 = fmaxf(r[1] - rho, 0.f), a2 = fmaxf(r[2] - rho, 0.f);
        float a3 = fmaxf(r[3] - rho, 0.f), a4 = fmaxf(r[4] - rho, 0.f);
        g_rhoz[row] = rho;
        g_sigz[row] = calibrate(a1, a2, a3, a4, TARGET_Z);
    }
}

// ---------------- K3: W1 / W2 / S + colsum (warp per row, float4 I/O) --------
__global__ __launch_bounds__(256) void k_ws(float* __restrict__ out) {
    __shared__ float s_rho[KC], s_isu[KC], s_cs[KC];
    int t = threadIdx.x;
    s_rho[t] = g_rhou[t];
    s_isu[t] = 1.0f / g_sigu[t];
    s_cs[t] = 0.f;
    __syncthreads();

    int lane = t & 31;
    int w = t >> 5;
    int wid = (blockIdx.x << 3) + w;
    const int wstride = gridDim.x << 3;
    const int c0 = lane * 4, c1 = 128 + lane * 4;
    float* outW1a = out;
    float* outS   = out + NKSZ;
    float* outW1b = out + 2 * NKSZ;

    float ru[8], iu[8];
#pragma unroll
    for (int j = 0; j < 4; j++) {
        ru[j] = s_rho[c0 + j];     iu[j] = s_isu[c0 + j];
        ru[4 + j] = s_rho[c1 + j]; iu[4 + j] = s_isu[c1 + j];
    }
    float cs[8];
#pragma unroll
    for (int j = 0; j < 8; j++) cs[j] = 0.f;

    for (int row = wid; row < NROWS; row += wstride) {
        float rho = g_rhoz[row];
        float isz = 1.0f / g_sigz[row];
        const float* dr = g_d + (size_t)row * KC;
        float4 d0 = *(const float4*)(dr + c0);
        float4 d1 = *(const float4*)(dr + c1);
        float dv[8] = {d0.x, d0.y, d0.z, d0.w, d1.x, d1.y, d1.z, d1.w};
        float w1v[8], sv[8];
        float sum = 0.f;
#pragma unroll
        for (int j = 0; j < 8; j++) {
            float w1 = __expf(-fmaxf(dv[j] - rho, 0.f) * isz);
            float w2 = __expf(-fmaxf(dv[j] - ru[j], 0.f) * iu[j]);
            float s = w1 + w2 - w1 * w2;
            w1v[j] = w1; sv[j] = s; sum += s;
        }
#pragma unroll
        for (int off = 16; off; off >>= 1) sum += __shfl_xor_sync(0xffffffffu, sum, off);
        float rinv = 1.0f / sum;
        float4 w1a = make_float4(w1v[0], w1v[1], w1v[2], w1v[3]);
        float4 w1b = make_float4(w1v[4], w1v[5], w1v[6], w1v[7]);
        float4 s0 = make_float4(sv[0] * rinv, sv[1] * rinv, sv[2] * rinv, sv[3] * rinv);
        float4 s1 = make_float4(sv[4] * rinv, sv[5] * rinv, sv[6] * rinv, sv[7] * rinv);
        size_t base = (size_t)row * KC;
        *(float4*)(outW1a + base + c0) = w1a;
        *(float4*)(outW1a + base + c1) = w1b;
        *(float4*)(outW1b + base + c0) = w1a;
        *(float4*)(outW1b + base + c1) = w1b;
        *(float4*)(outS + base + c0) = s0;
        *(float4*)(outS + base + c1) = s1;
        cs[0] += s0.x; cs[1] += s0.y; cs[2] += s0.z; cs[3] += s0.w;
        cs[4] += s1.x; cs[5] += s1.y; cs[6] += s1.z; cs[7] += s1.w;
    }
#pragma unroll
    for (int j = 0; j < 4; j++) {
        atomicAdd(&s_cs[c0 + j], cs[j]);
        atomicAdd(&s_cs[c1 + j], cs[4 + j]);
    }
    __syncthreads();
    atomicAdd(&g_colsum[t], s_cs[t]);
}

// ---------------- K4: Dmat (float4 I/O) ---------------------------------------
__global__ __launch_bounds__(256) void k_dmat(float* __restrict__ out) {
    __shared__ float s_ic[KC];
    int t = threadIdx.x;
    s_ic[t] = 1.0f / g_colsum[t];
    __syncthreads();

    const float* Sm = out + NKSZ;
    float* Dm = out + 3 * NKSZ;
    int lane = t & 31;
    int w = t >> 5;
    int wid = (blockIdx.x << 3) + w;
    const int wstride = gridDim.x << 3;
    const int c0 = lane * 4, c1 = 128 + lane * 4;

    float ic[8];
#pragma unroll
    for (int j = 0; j < 4; j++) {
        ic[j] = s_ic[c0 + j];
        ic[4 + j] = s_ic[c1 + j];
    }

    for (int row = wid; row < NROWS; row += wstride) {
        const float* sr = Sm + (size_t)row * KC;
        float4 v0 = *(const float4*)(sr + c0);
        float4 v1 = *(const float4*)(sr + c1);
        float sv[8] = {v0.x, v0.y, v0.z, v0.w, v1.x, v1.y, v1.z, v1.w};
        float tv[8];
        float sum = 0.f;
#pragma unroll
        for (int j = 0; j < 8; j++) {
            float q = sv[j] * sv[j] * ic[j];
            tv[j] = q; sum += q;
        }
#pragma unroll
        for (int off = 16; off; off >>= 1) sum += __shfl_xor_sync(0xffffffffu, sum, off);
        float rinv = 1.0f / sum;
        float4 o0 = make_float4(tv[0] * rinv, tv[1] * rinv, tv[2] * rinv, tv[3] * rinv);
        float4 o1 = make_float4(tv[4] * rinv, tv[5] * rinv, tv[6] * rinv, tv[7] * rinv);
        size_t base = (size_t)row * KC;
        *(float4*)(Dm + base + c0) = o0;
        *(float4*)(Dm + base + c1) = o1;
    }
}

// ---------------- launcher ---------------------------------------------------
extern "C" void kernel_launch(void* const* d_in, const int* in_sizes, int n_in,
                              void* d_out, int out_size) {
    (void)in_sizes; (void)n_in; (void)out_size;
    const float* z  = (const float*)d_in[0];
    const float* mu = (const float*)d_in[1];
    float* out = (float*)d_out;

    cudaFuncSetAttribute(k_gemm, cudaFuncAttributeMaxDynamicSharedMemorySize,
                         GSMEM_TOTAL);

    k_prep_mu<<<32, 256>>>(mu);                      // #1 (parallel now)
    k_gemm<<<NROWS / 128, 512, GSMEM_TOTAL>>>(z);    // #2
    k_reduce<<<288, 256>>>();                        // #3
    k_ws<<<2048, 256>>>(out);                        // #4 <- ncu slot
    k_dmat<<<2048, 256>>>(out);                      // #5
}

// round 13
// speedup vs baseline: 1.6988x; 1.1087x over previous
#include <cuda_runtime.h>
#include <cuda_bf16.h>
#include <math.h>
#include <stdint.h>

#define NROWS 65536
#define KC 256
#define DH 256
#define NKSZ ((size_t)NROWS * KC)
#define EPSV 1e-6f
#define SIGMA_HI_V 10000.0f
#define TARGET_Z 1.3219281f   /* log2(5)-1 */
#define TARGET_U 2.3219281f   /* log2(5)   */
#define INF_F __int_as_float(0x7f800000)
#define CAL_ITERS 64
#define NPART 512

// ---------------- scratch (device globals; no runtime allocation) ----------
__device__ float g_d[NKSZ];                 // 64MB distance matrix
__device__ uint4 g_mhi4[KC * 64];           // mu hi tf32-in-f32 (16B quads)
__device__ uint4 g_mlo4[KC * 64];           // mu lo tf32-in-f32
__device__ float g_m2[KC], g_ms[KC];
__device__ float g_relz[(size_t)NROWS * 5];
__device__ float g_rhoz[NROWS];
__device__ float g_sigz[NROWS];
__device__ float g_part1[NPART * 5 * KC];   // [cta][s][col]
__device__ float g_rhou[KC];
__device__ float g_sigu[KC];
__device__ float g_colsum[KC];

// ---------------- PTX helpers (baseline PTX only) ----------------------------
__device__ __forceinline__ uint32_t smem_u32(const void* p) {
    uint32_t a;
    asm("{ .reg .u64 t; cvta.to.shared.u64 t, %1; cvt.u32.u64 %0, t; }" : "=r"(a) : "l"(p));
    return a;
}

__device__ __forceinline__ uint32_t tf32u(float x) {
    uint32_t u;
    asm("cvt.rna.tf32.f32 %0, %1;" : "=r"(u) : "f"(x));
    return u;
}

__device__ __forceinline__ void ldmx4(uint32_t* r, uint32_t addr) {
    asm volatile("ldmatrix.sync.aligned.m8n8.x4.shared.b16 {%0,%1,%2,%3}, [%4];"
                 : "=r"(r[0]), "=r"(r[1]), "=r"(r[2]), "=r"(r[3]) : "r"(addr));
}

__device__ __forceinline__ void mma_tf32(float* d, const uint32_t* a, const uint32_t* b) {
    asm volatile(
        "mma.sync.aligned.m16n8k8.row.col.f32.tf32.tf32.f32 "
        "{%0,%1,%2,%3}, {%4,%5,%6,%7}, {%8,%9}, {%0,%1,%2,%3};"
        : "+f"(d[0]), "+f"(d[1]), "+f"(d[2]), "+f"(d[3])
        : "r"(a[0]), "r"(a[1]), "r"(a[2]), "r"(a[3]), "r"(b[0]), "r"(b[1]));
}

// ---------------- K0: mu prep (warp per row; parallel) ------------------------
__global__ __launch_bounds__(256) void k_prep_mu(const float* __restrict__ mu) {
    int row = blockIdx.x * 8 + (threadIdx.x >> 5);
    int lane = threadIdx.x & 31;
    const float* r = mu + (size_t)row * DH + lane * 8;
    float m2 = 0.f, ms = 0.f;
#pragma unroll
    for (int g = 0; g < 2; g++) {
        float4 v = *(const float4*)(r + g * 4);
        float x[4] = {v.x, v.y, v.z, v.w};
        uint32_t hi[4], lo[4];
#pragma unroll
        for (int q = 0; q < 4; q++) {
            m2 = fmaf(x[q], x[q], m2);
            ms += x[q];
            hi[q] = tf32u(x[q]);
            lo[q] = tf32u(x[q] - __uint_as_float(hi[q]));
        }
        g_mhi4[row * 64 + lane * 2 + g] = make_uint4(hi[0], hi[1], hi[2], hi[3]);
        g_mlo4[row * 64 + lane * 2 + g] = make_uint4(lo[0], lo[1], lo[2], lo[3]);
    }
#pragma unroll
    for (int off = 16; off; off >>= 1) {
        m2 += __shfl_xor_sync(0xffffffffu, m2, off);
        ms += __shfl_xor_sync(0xffffffffu, ms, off);
    }
    if (lane == 0) { g_m2[row] = m2; g_ms[row] = ms; }
}

__global__ void k_noop() {}

// ---------------- insertion helper ------------------------------------------
__device__ __forceinline__ void ins5(float v, float &t0, float &t1, float &t2,
                                     float &t3, float &t4) {
    if (v < t4) {
        if (v < t3) {
            t4 = t3;
            if (v < t2) {
                t3 = t2;
                if (v < t1) {
                    t2 = t1;
                    if (v < t0) { t1 = t0; t0 = v; } else t1 = v;
                } else t2 = v;
            } else t3 = v;
        } else t4 = v;
    }
}

// ---------------- K1: LEAN tf32-split GEMM + d (no top-5 fusion) -------------
#define LDS_A 68
#define TILE_LD 260
#define SA_HI 0
#define SA_LO 34816
#define SB_HI 69632
#define SB_LO 139264
#define ST_M2 208896
#define ST_MS 209920
#define ST_Z2 210944
#define ST_ZS 211456
#define GSMEM_TOTAL 211968

__global__ __launch_bounds__(512, 1) void k_gemm(const float* __restrict__ z) {
    extern __shared__ char smem[];
    const uint32_t sb = smem_u32(smem);
    const int t = threadIdx.x;
    const int wid = t >> 5, lane = t & 31;
    const int wr = wid >> 2, wc = wid & 3;
    const int rowBase = blockIdx.x * 128;

    float* s_m2 = (float*)(smem + ST_M2);
    float* s_ms = (float*)(smem + ST_MS);
    float* s_z2 = (float*)(smem + ST_Z2);
    float* s_zs = (float*)(smem + ST_ZS);
    if (t < 256) { s_m2[t] = g_m2[t]; s_ms[t] = g_ms[t]; }

    float acc[2][8][4];
#pragma unroll
    for (int mt = 0; mt < 2; mt++)
#pragma unroll
        for (int j = 0; j < 8; j++)
#pragma unroll
            for (int q = 0; q < 4; q++) acc[mt][j][q] = 0.f;

    const int ar = t >> 2, aq = t & 3;
    const float* zrow = z + (size_t)(rowBase + ar) * DH + aq * 16;
    float z2p = 0.f, zsp = 0.f;

    const uint32_t a_off = ((uint32_t)(wr * 32 + (lane & 15)) * LDS_A +
                            ((lane >> 4) << 2)) * 4;
    const uint32_t b_off = ((uint32_t)(wc * 64 + ((lane >> 4) << 3) + (lane & 7)) * LDS_A +
                            ((lane & 8) >> 1)) * 4;

#pragma unroll 1
    for (int c = 0; c < 4; c++) {
        __syncthreads();
        {
            const float4* src = (const float4*)(zrow + c * 64);
            uint32_t off = ((uint32_t)ar * LDS_A + aq * 16) * 4;
#pragma unroll
            for (int g = 0; g < 4; g++) {
                float4 v = src[g];
                z2p = fmaf(v.x, v.x, fmaf(v.y, v.y, fmaf(v.z, v.z, fmaf(v.w, v.w, z2p))));
                zsp += v.x + v.y + v.z + v.w;
                uint32_t hx = tf32u(v.x), hy = tf32u(v.y);
                uint32_t hz = tf32u(v.z), hw = tf32u(v.w);
                float4 hv = make_float4(__uint_as_float(hx), __uint_as_float(hy),
                                        __uint_as_float(hz), __uint_as_float(hw));
                float4 lv = make_float4(
                    __uint_as_float(tf32u(v.x - hv.x)), __uint_as_float(tf32u(v.y - hv.y)),
                    __uint_as_float(tf32u(v.z - hv.z)), __uint_as_float(tf32u(v.w - hv.w)));
                *(float4*)(smem + SA_HI + off + g * 16) = hv;
                *(float4*)(smem + SA_LO + off + g * 16) = lv;
            }
        }
#pragma unroll
        for (int i = 0; i < 8; i++) {
            int e = t + 512 * i;
            int row = e >> 4, q = e & 15;
            uint32_t off = ((uint32_t)row * LDS_A + q * 4) * 4;
            *(uint4*)(smem + SB_HI + off) = g_mhi4[row * 64 + c * 16 + q];
            *(uint4*)(smem + SB_LO + off) = g_mlo4[row * 64 + c * 16 + q];
        }
        __syncthreads();

#pragma unroll
        for (int ks = 0; ks < 8; ks++) {
            const uint32_t kb = (uint32_t)ks * 32;
            uint32_t ah[2][4], al[2][4];
            ldmx4(ah[0], sb + SA_HI + a_off + kb);
            ldmx4(ah[1], sb + SA_HI + a_off + kb + 16 * LDS_A * 4);
            ldmx4(al[0], sb + SA_LO + a_off + kb);
            ldmx4(al[1], sb + SA_LO + a_off + kb + 16 * LDS_A * 4);
#pragma unroll
            for (int pp = 0; pp < 2; pp++) {
                const int p0 = 2 * pp, p1 = 2 * pp + 1;
                const uint32_t pb0 = (uint32_t)p0 * 16 * LDS_A * 4;
                const uint32_t pb1 = (uint32_t)p1 * 16 * LDS_A * 4;
                uint32_t bh0[4], bh1[4];
                ldmx4(bh0, sb + SB_HI + b_off + kb + pb0);
                ldmx4(bh1, sb + SB_HI + b_off + kb + pb1);
                mma_tf32(acc[0][2 * p0],     ah[0], &bh0[0]);
                mma_tf32(acc[0][2 * p0 + 1], ah[0], &bh0[2]);
                mma_tf32(acc[1][2 * p0],     ah[1], &bh0[0]);
                mma_tf32(acc[1][2 * p0 + 1], ah[1], &bh0[2]);
                mma_tf32(acc[0][2 * p1],     ah[0], &bh1[0]);
                mma_tf32(acc[0][2 * p1 + 1], ah[0], &bh1[2]);
                mma_tf32(acc[1][2 * p1],     ah[1], &bh1[0]);
                mma_tf32(acc[1][2 * p1 + 1], ah[1], &bh1[2]);
                uint32_t bl0[4], bl1[4];
                ldmx4(bl0, sb + SB_LO + b_off + kb + pb0);
                ldmx4(bl1, sb + SB_LO + b_off + kb + pb1);
                mma_tf32(acc[0][2 * p0],     al[0], &bh0[0]);
                mma_tf32(acc[0][2 * p0 + 1], al[0], &bh0[2]);
                mma_tf32(acc[1][2 * p0],     al[1], &bh0[0]);
                mma_tf32(acc[1][2 * p0 + 1], al[1], &bh0[2]);
                mma_tf32(acc[0][2 * p1],     al[0], &bh1[0]);
                mma_tf32(acc[0][2 * p1 + 1], al[0], &bh1[2]);
                mma_tf32(acc[1][2 * p1],     al[1], &bh1[0]);
                mma_tf32(acc[1][2 * p1 + 1], al[1], &bh1[2]);
                mma_tf32(acc[0][2 * p0],     ah[0], &bl0[0]);
                mma_tf32(acc[0][2 * p0 + 1], ah[0], &bl0[2]);
                mma_tf32(acc[1][2 * p0],     ah[1], &bl0[0]);
                mma_tf32(acc[1][2 * p0 + 1], ah[1], &bl0[2]);
                mma_tf32(acc[0][2 * p1],     ah[0], &bl1[0]);
                mma_tf32(acc[0][2 * p1 + 1], ah[0], &bl1[2]);
                mma_tf32(acc[1][2 * p1],     ah[1], &bl1[0]);
                mma_tf32(acc[1][2 * p1 + 1], ah[1], &bl1[2]);
            }
        }
    }

    z2p += __shfl_xor_sync(0xffffffffu, z2p, 1);
    z2p += __shfl_xor_sync(0xffffffffu, z2p, 2);
    zsp += __shfl_xor_sync(0xffffffffu, zsp, 1);
    zsp += __shfl_xor_sync(0xffffffffu, zsp, 2);
    if (aq == 0) { s_z2[ar] = z2p; s_zs[ar] = zsp; }
    __syncthreads();

    float* tile = (float*)smem;
    const float cterm = (float)DH * EPSV * EPSV;
#pragma unroll
    for (int mt = 0; mt < 2; mt++) {
        const int r0 = wr * 32 + mt * 16 + (lane >> 2);
        const float z2va = s_z2[r0], zsva = s_zs[r0];
        const float z2vb = s_z2[r0 + 8], zsvb = s_zs[r0 + 8];
#pragma unroll
        for (int nt = 0; nt < 8; nt++) {
            const int c0 = wc * 64 + nt * 8 + (lane & 3) * 2;
            float m20 = s_m2[c0], ms0 = s_ms[c0];
            float m21 = s_m2[c0 + 1], ms1 = s_ms[c0 + 1];
            float d00 = z2va + m20 - 2.f * acc[mt][nt][0] + 2.f * EPSV * (zsva - ms0) + cterm;
            float d01 = z2va + m21 - 2.f * acc[mt][nt][1] + 2.f * EPSV * (zsva - ms1) + cterm;
            float d10 = z2vb + m20 - 2.f * acc[mt][nt][2] + 2.f * EPSV * (zsvb - ms0) + cterm;
            float d11 = z2vb + m21 - 2.f * acc[mt][nt][3] + 2.f * EPSV * (zsvb - ms1) + cterm;
            tile[r0 * TILE_LD + c0]           = sqrtf(fmaxf(d00, 0.f));
            tile[r0 * TILE_LD + c0 + 1]       = sqrtf(fmaxf(d01, 0.f));
            tile[(r0 + 8) * TILE_LD + c0]     = sqrtf(fmaxf(d10, 0.f));
            tile[(r0 + 8) * TILE_LD + c0 + 1] = sqrtf(fmaxf(d11, 0.f));
        }
    }
    __syncthreads();

#pragma unroll
    for (int i = 0; i < 16; i++) {
        int e = t + 512 * i;
        int row = e >> 6, c4 = e & 63;
        float4 v = *(const float4*)&tile[row * TILE_LD + c4 * 4];
        *(float4*)&g_d[(size_t)(rowBase + row) * KC + c4 * 4] = v;
    }
}

// ---------------- K2: top-5 reductions over g_d (row + column partials) ------
__global__ __launch_bounds__(256) void k_top() {
    const int rowBase = blockIdx.x * 128;
    const int t = threadIdx.x;
    const int w = t >> 5, lane = t & 31;

    // ---- pass A: row top-5 (warp handles 16 rows); warms L2 with this tile --
#pragma unroll 1
    for (int rr = 0; rr < 16; rr++) {
        int row = rowBase + w * 16 + rr;
        const float* dr = g_d + (size_t)row * KC;
        float4 d0 = *(const float4*)(dr + lane * 4);
        float4 d1 = *(const float4*)(dr + 128 + lane * 4);
        float t0 = INF_F, t1 = INF_F, t2 = INF_F, t3 = INF_F, t4 = INF_F;
        ins5(d0.x, t0, t1, t2, t3, t4); ins5(d0.y, t0, t1, t2, t3, t4);
        ins5(d0.z, t0, t1, t2, t3, t4); ins5(d0.w, t0, t1, t2, t3, t4);
        ins5(d1.x, t0, t1, t2, t3, t4); ins5(d1.y, t0, t1, t2, t3, t4);
        ins5(d1.z, t0, t1, t2, t3, t4); ins5(d1.w, t0, t1, t2, t3, t4);
#pragma unroll
        for (int off = 16; off; off >>= 1) {
            float o0 = __shfl_xor_sync(0xffffffffu, t0, off);
            float o1 = __shfl_xor_sync(0xffffffffu, t1, off);
            float o2 = __shfl_xor_sync(0xffffffffu, t2, off);
            float o3 = __shfl_xor_sync(0xffffffffu, t3, off);
            float o4 = __shfl_xor_sync(0xffffffffu, t4, off);
            ins5(o0, t0, t1, t2, t3, t4);
            ins5(o1, t0, t1, t2, t3, t4);
            ins5(o2, t0, t1, t2, t3, t4);
            ins5(o3, t0, t1, t2, t3, t4);
            ins5(o4, t0, t1, t2, t3, t4);
        }
        if (lane == 0) {
            float* rp = g_relz + (size_t)row * 5;
            rp[0] = t0; rp[1] = t1; rp[2] = t2; rp[3] = t3; rp[4] = t4;
        }
    }

    // ---- pass B: column top-5 partials (thread per column; L2-hot reads) ----
    {
        float t0 = INF_F, t1 = INF_F, t2 = INF_F, t3 = INF_F, t4 = INF_F;
        const float* p = g_d + (size_t)rowBase * KC + t;
#pragma unroll 4
        for (int r = 0; r < 128; r++)
            ins5(p[(size_t)r * KC], t0, t1, t2, t3, t4);
        float* pp = g_part1 + (size_t)blockIdx.x * 5 * KC + t;
        pp[0 * KC] = t0; pp[1 * KC] = t1; pp[2 * KC] = t2;
        pp[3 * KC] = t3; pp[4 * KC] = t4;
    }
}

// ---------------- bisection (mirrors reference update rule) -----------------
__device__ __forceinline__ float calibrate(float a1, float a2, float a3, float a4,
                                           float target) {
    float mid0 = 0.f, mid1 = SIGMA_HI_V, sigma = 1.f;
#pragma unroll 1
    for (int it = 0; it < CAL_ITERS; it++) {
        float inv = __frcp_rn(sigma);
        float cur = 1.f + __expf(-a1 * inv) + __expf(-a2 * inv) +
                    __expf(-a3 * inv) + __expf(-a4 * inv);
        if (cur > target) mid1 = sigma; else mid0 = sigma;
        sigma = 0.5f * (mid0 + mid1);
    }
    return sigma;
}

// ---------------- K3: fused reductions ---------------------------------------
__global__ __launch_bounds__(256) void k_reduce() {
    int b = blockIdx.x;
    if (b < 32) {
        int w = threadIdx.x >> 5, lane = threadIdx.x & 31;
        int col = b * 8 + w;
        float t0 = INF_F, t1 = INF_F, t2 = INF_F, t3 = INF_F, t4 = INF_F;
        for (int p = lane; p < NPART; p += 32) {
            const float* pp = g_part1 + (size_t)p * 5 * KC + col;
#pragma unroll
            for (int s = 0; s < 5; s++) ins5(pp[s * KC], t0, t1, t2, t3, t4);
        }
#pragma unroll
        for (int off = 16; off; off >>= 1) {
            float o0 = __shfl_xor_sync(0xffffffffu, t0, off);
            float o1 = __shfl_xor_sync(0xffffffffu, t1, off);
            float o2 = __shfl_xor_sync(0xffffffffu, t2, off);
            float o3 = __shfl_xor_sync(0xffffffffu, t3, off);
            float o4 = __shfl_xor_sync(0xffffffffu, t4, off);
            ins5(o0, t0, t1, t2, t3, t4);
            ins5(o1, t0, t1, t2, t3, t4);
            ins5(o2, t0, t1, t2, t3, t4);
            ins5(o3, t0, t1, t2, t3, t4);
            ins5(o4, t0, t1, t2, t3, t4);
        }
        if (lane == 0) {
            float rho = t0;
            g_rhou[col] = rho;
            g_colsum[col] = 0.f;
            float a1 = fmaxf(t1 - rho, 0.f), a2 = fmaxf(t2 - rho, 0.f);
            float a3 = fmaxf(t3 - rho, 0.f), a4 = fmaxf(t4 - rho, 0.f);
            g_sigu[col] = calibrate(a1, a2, a3, a4, TARGET_U);
        }
    } else {
        int row = (b - 32) * 256 + threadIdx.x;
        const float* r = g_relz + (size_t)row * 5;
        float rho = r[0];
        float a1 = fmaxf(r[1] - rho, 0.f), a2 = fmaxf(r[2] - rho, 0.f);
        float a3 = fmaxf(r[3] - rho, 0.f), a4 = fmaxf(r[4] - rho, 0.f);
        g_rhoz[row] = rho;
        g_sigz[row] = calibrate(a1, a2, a3, a4, TARGET_Z);
    }
}

// ---------------- K4: W1 / W2 / S + colsum (warp per row, float4 I/O) --------
__global__ __launch_bounds__(256) void k_ws(float* __restrict__ out) {
    __shared__ float s_rho[KC], s_isu[KC], s_cs[KC];
    int t = threadIdx.x;
    s_rho[t] = g_rhou[t];
    s_isu[t] = 1.0f / g_sigu[t];
    s_cs[t] = 0.f;
    __syncthreads();

    int lane = t & 31;
    int w = t >> 5;
    int wid = (blockIdx.x << 3) + w;
    const int wstride = gridDim.x << 3;
    const int c0 = lane * 4, c1 = 128 + lane * 4;
    float* outW1a = out;
    float* outS   = out + NKSZ;
    float* outW1b = out + 2 * NKSZ;

    float ru[8], iu[8];
#pragma unroll
    for (int j = 0; j < 4; j++) {
        ru[j] = s_rho[c0 + j];     iu[j] = s_isu[c0 + j];
        ru[4 + j] = s_rho[c1 + j]; iu[4 + j] = s_isu[c1 + j];
    }
    float cs[8];
#pragma unroll
    for (int j = 0; j < 8; j++) cs[j] = 0.f;

    for (int row = wid; row < NROWS; row += wstride) {
        float rho = g_rhoz[row];
        float isz = 1.0f / g_sigz[row];
        const float* dr = g_d + (size_t)row * KC;
        float4 d0 = *(const float4*)(dr + c0);
        float4 d1 = *(const float4*)(dr + c1);
        float dv[8] = {d0.x, d0.y, d0.z, d0.w, d1.x, d1.y, d1.z, d1.w};
        float w1v[8], sv[8];
        float sum = 0.f;
#pragma unroll
        for (int j = 0; j < 8; j++) {
            float w1 = __expf(-fmaxf(dv[j] - rho, 0.f) * isz);
            float w2 = __expf(-fmaxf(dv[j] - ru[j], 0.f) * iu[j]);
            float s = w1 + w2 - w1 * w2;
            w1v[j] = w1; sv[j] = s; sum += s;
        }
#pragma unroll
        for (int off = 16; off; off >>= 1) sum += __shfl_xor_sync(0xffffffffu, sum, off);
        float rinv = 1.0f / sum;
        float4 w1a = make_float4(w1v[0], w1v[1], w1v[2], w1v[3]);
        float4 w1b = make_float4(w1v[4], w1v[5], w1v[6], w1v[7]);
        float4 s0 = make_float4(sv[0] * rinv, sv[1] * rinv, sv[2] * rinv, sv[3] * rinv);
        float4 s1 = make_float4(sv[4] * rinv, sv[5] * rinv, sv[6] * rinv, sv[7] * rinv);
        size_t base = (size_t)row * KC;
        *(float4*)(outW1a + base + c0) = w1a;
        *(float4*)(outW1a + base + c1) = w1b;
        *(float4*)(outW1b + base + c0) = w1a;
        *(float4*)(outW1b + base + c1) = w1b;
        *(float4*)(outS + base + c0) = s0;
        *(float4*)(outS + base + c1) = s1;
        cs[0] += s0.x; cs[1] += s0.y; cs[2] += s0.z; cs[3] += s0.w;
        cs[4] += s1.x; cs[5] += s1.y; cs[6] += s1.z; cs[7] += s1.w;
    }
#pragma unroll
    for (int j = 0; j < 4; j++) {
        atomicAdd(&s_cs[c0 + j], cs[j]);
        atomicAdd(&s_cs[c1 + j], cs[4 + j]);
    }
    __syncthreads();
    atomicAdd(&g_colsum[t], s_cs[t]);
}

// ---------------- K5: Dmat (float4 I/O) ---------------------------------------
__global__ __launch_bounds__(256) void k_dmat(float* __restrict__ out) {
    __shared__ float s_ic[KC];
    int t = threadIdx.x;
    s_ic[t] = 1.0f / g_colsum[t];
    __syncthreads();

    const float* Sm = out + NKSZ;
    float* Dm = out + 3 * NKSZ;
    int lane = t & 31;
    int w = t >> 5;
    int wid = (blockIdx.x << 3) + w;
    const int wstride = gridDim.x << 3;
    const int c0 = lane * 4, c1 = 128 + lane * 4;

    float ic[8];
#pragma unroll
    for (int j = 0; j < 4; j++) {
        ic[j] = s_ic[c0 + j];
        ic[4 + j] = s_ic[c1 + j];
    }

    for (int row = wid; row < NROWS; row += wstride) {
        const float* sr = Sm + (size_t)row * KC;
        float4 v0 = *(const float4*)(sr + c0);
        float4 v1 = *(const float4*)(sr + c1);
        float sv[8] = {v0.x, v0.y, v0.z, v0.w, v1.x, v1.y, v1.z, v1.w};
        float tv[8];
        float sum = 0.f;
#pragma unroll
        for (int j = 0; j < 8; j++) {
            float q = sv[j] * sv[j] * ic[j];
            tv[j] = q; sum += q;
        }
#pragma unroll
        for (int off = 16; off; off >>= 1) sum += __shfl_xor_sync(0xffffffffu, sum, off);
        float rinv = 1.0f / sum;
        float4 o0 = make_float4(tv[0] * rinv, tv[1] * rinv, tv[2] * rinv, tv[3] * rinv);
        float4 o1 = make_float4(tv[4] * rinv, tv[5] * rinv, tv[6] * rinv, tv[7] * rinv);
        size_t base = (size_t)row * KC;
        *(float4*)(Dm + base + c0) = o0;
        *(float4*)(Dm + base + c1) = o1;
    }
}

// ---------------- launcher ---------------------------------------------------
extern "C" void kernel_launch(void* const* d_in, const int* in_sizes, int n_in,
                              void* d_out, int out_size) {
    (void)in_sizes; (void)n_in; (void)out_size;
    const float* z  = (const float*)d_in[0];
    const float* mu = (const float*)d_in[1];
    float* out = (float*)d_out;

    cudaFuncSetAttribute(k_gemm, cudaFuncAttributeMaxDynamicSharedMemorySize,
                         GSMEM_TOTAL);

    k_prep_mu<<<32, 256>>>(mu);                      // #1
    k_noop<<<1, 32>>>();                             // #2
    k_noop<<<1, 32>>>();                             // #3
    k_gemm<<<NROWS / 128, 512, GSMEM_TOTAL>>>(z);    // #4 <- ncu slot
    k_top<<<NROWS / 128, 256>>>();                   // #5
    k_reduce<<<288, 256>>>();                        // #6
    k_ws<<<1024, 256>>>(out);                        // #7
    k_dmat<<<1024, 256>>>(out);                      // #8
}

// round 14
// speedup vs baseline: 1.6995x; 1.0004x over previous
#include <cuda_runtime.h>
#include <cuda_bf16.h>
#include <math.h>
#include <stdint.h>

#define NROWS 65536
#define KC 256
#define DH 256
#define NKSZ ((size_t)NROWS * KC)
#define EPSV 1e-6f
#define SIGMA_HI_V 10000.0f
#define TARGET_Z 1.3219281f   /* log2(5)-1 */
#define TARGET_U 2.3219281f   /* log2(5)   */
#define INF_F __int_as_float(0x7f800000)
#define CAL_ITERS 64
#define NPART 512

// ---------------- scratch (device globals; no runtime allocation) ----------
__device__ float g_d[NKSZ];                 // 64MB distance matrix
__device__ uint4 g_mhi4[KC * 64];           // mu hi tf32-in-f32 (16B quads)
__device__ uint4 g_mlo4[KC * 64];           // mu lo tf32-in-f32
__device__ float g_m2[KC], g_ms[KC];
__device__ float g_relz[(size_t)NROWS * 5];
__device__ float g_rhoz[NROWS];
__device__ float g_sigz[NROWS];
__device__ float g_part1[NPART * 5 * KC];   // [cta][s][col]
__device__ float g_rhou[KC];
__device__ float g_sigu[KC];
__device__ float g_colsum[KC];

// ---------------- PTX helpers (baseline PTX only) ----------------------------
__device__ __forceinline__ uint32_t smem_u32(const void* p) {
    uint32_t a;
    asm("{ .reg .u64 t; cvta.to.shared.u64 t, %1; cvt.u32.u64 %0, t; }" : "=r"(a) : "l"(p));
    return a;
}

__device__ __forceinline__ uint32_t tf32u(float x) {
    uint32_t u;
    asm("cvt.rna.tf32.f32 %0, %1;" : "=r"(u) : "f"(x));
    return u;
}

__device__ __forceinline__ void ldmx4(uint32_t* r, uint32_t addr) {
    asm volatile("ldmatrix.sync.aligned.m8n8.x4.shared.b16 {%0,%1,%2,%3}, [%4];"
                 : "=r"(r[0]), "=r"(r[1]), "=r"(r[2]), "=r"(r[3]) : "r"(addr));
}

__device__ __forceinline__ void mma_tf32(float* d, const uint32_t* a, const uint32_t* b) {
    asm volatile(
        "mma.sync.aligned.m16n8k8.row.col.f32.tf32.tf32.f32 "
        "{%0,%1,%2,%3}, {%4,%5,%6,%7}, {%8,%9}, {%0,%1,%2,%3};"
        : "+f"(d[0]), "+f"(d[1]), "+f"(d[2]), "+f"(d[3])
        : "r"(a[0]), "r"(a[1]), "r"(a[2]), "r"(a[3]), "r"(b[0]), "r"(b[1]));
}

// ---------------- K0: mu prep (warp per row; parallel) ------------------------
__global__ __launch_bounds__(256) void k_prep_mu(const float* __restrict__ mu) {
    int row = blockIdx.x * 8 + (threadIdx.x >> 5);
    int lane = threadIdx.x & 31;
    const float* r = mu + (size_t)row * DH + lane * 8;
    float m2 = 0.f, ms = 0.f;
#pragma unroll
    for (int g = 0; g < 2; g++) {
        float4 v = *(const float4*)(r + g * 4);
        float x[4] = {v.x, v.y, v.z, v.w};
        uint32_t hi[4], lo[4];
#pragma unroll
        for (int q = 0; q < 4; q++) {
            m2 = fmaf(x[q], x[q], m2);
            ms += x[q];
            hi[q] = tf32u(x[q]);
            lo[q] = tf32u(x[q] - __uint_as_float(hi[q]));
        }
        g_mhi4[row * 64 + lane * 2 + g] = make_uint4(hi[0], hi[1], hi[2], hi[3]);
        g_mlo4[row * 64 + lane * 2 + g] = make_uint4(lo[0], lo[1], lo[2], lo[3]);
    }
#pragma unroll
    for (int off = 16; off; off >>= 1) {
        m2 += __shfl_xor_sync(0xffffffffu, m2, off);
        ms += __shfl_xor_sync(0xffffffffu, ms, off);
    }
    if (lane == 0) { g_m2[row] = m2; g_ms[row] = ms; }
}

__global__ void k_noop() {}

// ---------------- insertion helper ------------------------------------------
__device__ __forceinline__ void ins5(float v, float &t0, float &t1, float &t2,
                                     float &t3, float &t4) {
    if (v < t4) {
        if (v < t3) {
            t4 = t3;
            if (v < t2) {
                t3 = t2;
                if (v < t1) {
                    t2 = t1;
                    if (v < t0) { t1 = t0; t0 = v; } else t1 = v;
                } else t2 = v;
            } else t3 = v;
        } else t4 = v;
    }
}

// ---------------- K1: LEAN tf32-split GEMM + d --------------------------------
// CTA 128x256, 16 warps, warp tile 32x64, K in 4 chunks of 64, 8 k8-steps.
// Per ks: full-width passes hh(16) -> lh(16) -> hl(16); RAW distance 16 mmas.
#define LDS_A 68
#define TILE_LD 260
#define SA_HI 0
#define SA_LO 34816
#define SB_HI 69632
#define SB_LO 139264
#define ST_M2 208896
#define ST_MS 209920
#define ST_Z2 210944
#define ST_ZS 211456
#define GSMEM_TOTAL 211968

__global__ __launch_bounds__(512, 1) void k_gemm(const float* __restrict__ z) {
    extern __shared__ char smem[];
    const uint32_t sb = smem_u32(smem);
    const int t = threadIdx.x;
    const int wid = t >> 5, lane = t & 31;
    const int wr = wid >> 2, wc = wid & 3;
    const int rowBase = blockIdx.x * 128;

    float* s_m2 = (float*)(smem + ST_M2);
    float* s_ms = (float*)(smem + ST_MS);
    float* s_z2 = (float*)(smem + ST_Z2);
    float* s_zs = (float*)(smem + ST_ZS);
    if (t < 256) { s_m2[t] = g_m2[t]; s_ms[t] = g_ms[t]; }

    float acc[2][8][4];
#pragma unroll
    for (int mt = 0; mt < 2; mt++)
#pragma unroll
        for (int j = 0; j < 8; j++)
#pragma unroll
            for (int q = 0; q < 4; q++) acc[mt][j][q] = 0.f;

    const int ar = t >> 2, aq = t & 3;
    const float* zrow = z + (size_t)(rowBase + ar) * DH + aq * 16;
    float z2p = 0.f, zsp = 0.f;

    const uint32_t a_off = ((uint32_t)(wr * 32 + (lane & 15)) * LDS_A +
                            ((lane >> 4) << 2)) * 4;
    const uint32_t b_off = ((uint32_t)(wc * 64 + ((lane >> 4) << 3) + (lane & 7)) * LDS_A +
                            ((lane & 8) >> 1)) * 4;

#pragma unroll 1
    for (int c = 0; c < 4; c++) {
        __syncthreads();
        {
            const float4* src = (const float4*)(zrow + c * 64);
            uint32_t off = ((uint32_t)ar * LDS_A + aq * 16) * 4;
#pragma unroll
            for (int g = 0; g < 4; g++) {
                float4 v = src[g];
                z2p = fmaf(v.x, v.x, fmaf(v.y, v.y, fmaf(v.z, v.z, fmaf(v.w, v.w, z2p))));
                zsp += v.x + v.y + v.z + v.w;
                uint32_t hx = tf32u(v.x), hy = tf32u(v.y);
                uint32_t hz = tf32u(v.z), hw = tf32u(v.w);
                float4 hv = make_float4(__uint_as_float(hx), __uint_as_float(hy),
                                        __uint_as_float(hz), __uint_as_float(hw));
                float4 lv = make_float4(
                    __uint_as_float(tf32u(v.x - hv.x)), __uint_as_float(tf32u(v.y - hv.y)),
                    __uint_as_float(tf32u(v.z - hv.z)), __uint_as_float(tf32u(v.w - hv.w)));
                *(float4*)(smem + SA_HI + off + g * 16) = hv;
                *(float4*)(smem + SA_LO + off + g * 16) = lv;
            }
        }
#pragma unroll
        for (int i = 0; i < 8; i++) {
            int e = t + 512 * i;
            int row = e >> 4, q = e & 15;
            uint32_t off = ((uint32_t)row * LDS_A + q * 4) * 4;
            *(uint4*)(smem + SB_HI + off) = g_mhi4[row * 64 + c * 16 + q];
            *(uint4*)(smem + SB_LO + off) = g_mlo4[row * 64 + c * 16 + q];
        }
        __syncthreads();

#pragma unroll
        for (int ks = 0; ks < 8; ks++) {
            const uint32_t kb = (uint32_t)ks * 32;
            uint32_t ah[2][4], al[2][4];
            ldmx4(ah[0], sb + SA_HI + a_off + kb);
            ldmx4(ah[1], sb + SA_HI + a_off + kb + 16 * LDS_A * 4);
            ldmx4(al[0], sb + SA_LO + a_off + kb);
            ldmx4(al[1], sb + SA_LO + a_off + kb + 16 * LDS_A * 4);

            uint32_t bh[4][4];
#pragma unroll
            for (int p = 0; p < 4; p++)
                ldmx4(bh[p], sb + SB_HI + b_off + kb + (uint32_t)p * 16 * LDS_A * 4);

            // hh pass: 16 mmas, all distinct accumulators
#pragma unroll
            for (int p = 0; p < 4; p++) {
                mma_tf32(acc[0][2 * p],     ah[0], &bh[p][0]);
                mma_tf32(acc[0][2 * p + 1], ah[0], &bh[p][2]);
                mma_tf32(acc[1][2 * p],     ah[1], &bh[p][0]);
                mma_tf32(acc[1][2 * p + 1], ah[1], &bh[p][2]);
            }
            // lh pass: RAW distance 16 from hh
#pragma unroll
            for (int p = 0; p < 4; p++) {
                mma_tf32(acc[0][2 * p],     al[0], &bh[p][0]);
                mma_tf32(acc[0][2 * p + 1], al[0], &bh[p][2]);
                mma_tf32(acc[1][2 * p],     al[1], &bh[p][0]);
                mma_tf32(acc[1][2 * p + 1], al[1], &bh[p][2]);
            }
            // lo B load (latency overlapped by lh pass retirement)
            uint32_t bl[4][4];
#pragma unroll
            for (int p = 0; p < 4; p++)
                ldmx4(bl[p], sb + SB_LO + b_off + kb + (uint32_t)p * 16 * LDS_A * 4);
            // hl pass
#pragma unroll
            for (int p = 0; p < 4; p++) {
                mma_tf32(acc[0][2 * p],     ah[0], &bl[p][0]);
                mma_tf32(acc[0][2 * p + 1], ah[0], &bl[p][2]);
                mma_tf32(acc[1][2 * p],     ah[1], &bl[p][0]);
                mma_tf32(acc[1][2 * p + 1], ah[1], &bl[p][2]);
            }
        }
    }

    z2p += __shfl_xor_sync(0xffffffffu, z2p, 1);
    z2p += __shfl_xor_sync(0xffffffffu, z2p, 2);
    zsp += __shfl_xor_sync(0xffffffffu, zsp, 1);
    zsp += __shfl_xor_sync(0xffffffffu, zsp, 2);
    if (aq == 0) { s_z2[ar] = z2p; s_zs[ar] = zsp; }
    __syncthreads();

    float* tile = (float*)smem;
    const float cterm = (float)DH * EPSV * EPSV;
#pragma unroll
    for (int mt = 0; mt < 2; mt++) {
        const int r0 = wr * 32 + mt * 16 + (lane >> 2);
        const float z2va = s_z2[r0], zsva = s_zs[r0];
        const float z2vb = s_z2[r0 + 8], zsvb = s_zs[r0 + 8];
#pragma unroll
        for (int nt = 0; nt < 8; nt++) {
            const int c0 = wc * 64 + nt * 8 + (lane & 3) * 2;
            float m20 = s_m2[c0], ms0 = s_ms[c0];
            float m21 = s_m2[c0 + 1], ms1 = s_ms[c0 + 1];
            float d00 = z2va + m20 - 2.f * acc[mt][nt][0] + 2.f * EPSV * (zsva - ms0) + cterm;
            float d01 = z2va + m21 - 2.f * acc[mt][nt][1] + 2.f * EPSV * (zsva - ms1) + cterm;
            float d10 = z2vb + m20 - 2.f * acc[mt][nt][2] + 2.f * EPSV * (zsvb - ms0) + cterm;
            float d11 = z2vb + m21 - 2.f * acc[mt][nt][3] + 2.f * EPSV * (zsvb - ms1) + cterm;
            tile[r0 * TILE_LD + c0]           = sqrtf(fmaxf(d00, 0.f));
            tile[r0 * TILE_LD + c0 + 1]       = sqrtf(fmaxf(d01, 0.f));
            tile[(r0 + 8) * TILE_LD + c0]     = sqrtf(fmaxf(d10, 0.f));
            tile[(r0 + 8) * TILE_LD + c0 + 1] = sqrtf(fmaxf(d11, 0.f));
        }
    }
    __syncthreads();

#pragma unroll
    for (int i = 0; i < 16; i++) {
        int e = t + 512 * i;
        int row = e >> 6, c4 = e & 63;
        float4 v = *(const float4*)&tile[row * TILE_LD + c4 * 4];
        *(float4*)&g_d[(size_t)(rowBase + row) * KC + c4 * 4] = v;
    }
}

// ---------------- K2: top-5 reductions over g_d (row + column partials) ------
__global__ __launch_bounds__(256) void k_top() {
    const int rowBase = blockIdx.x * 128;
    const int t = threadIdx.x;
    const int w = t >> 5, lane = t & 31;

    // ---- pass A: row top-5 (warp handles 16 rows) ----------------------------
#pragma unroll 1
    for (int rr = 0; rr < 16; rr++) {
        int row = rowBase + w * 16 + rr;
        const float* dr = g_d + (size_t)row * KC;
        float4 d0 = *(const float4*)(dr + lane * 4);
        float4 d1 = *(const float4*)(dr + 128 + lane * 4);
        float t0 = INF_F, t1 = INF_F, t2 = INF_F, t3 = INF_F, t4 = INF_F;
        ins5(d0.x, t0, t1, t2, t3, t4); ins5(d0.y, t0, t1, t2, t3, t4);
        ins5(d0.z, t0, t1, t2, t3, t4); ins5(d0.w, t0, t1, t2, t3, t4);
        ins5(d1.x, t0, t1, t2, t3, t4); ins5(d1.y, t0, t1, t2, t3, t4);
        ins5(d1.z, t0, t1, t2, t3, t4); ins5(d1.w, t0, t1, t2, t3, t4);
#pragma unroll
        for (int off = 16; off; off >>= 1) {
            float o0 = __shfl_xor_sync(0xffffffffu, t0, off);
            float o1 = __shfl_xor_sync(0xffffffffu, t1, off);
            float o2 = __shfl_xor_sync(0xffffffffu, t2, off);
            float o3 = __shfl_xor_sync(0xffffffffu, t3, off);
            float o4 = __shfl_xor_sync(0xffffffffu, t4, off);
            ins5(o0, t0, t1, t2, t3, t4);
            ins5(o1, t0, t1, t2, t3, t4);
            ins5(o2, t0, t1, t2, t3, t4);
            ins5(o3, t0, t1, t2, t3, t4);
            ins5(o4, t0, t1, t2, t3, t4);
        }
        if (lane == 0) {
            float* rp = g_relz + (size_t)row * 5;
            rp[0] = t0; rp[1] = t1; rp[2] = t2; rp[3] = t3; rp[4] = t4;
        }
    }

    // ---- pass B: column top-5 partials (thread per column; L2-hot reads) ----
    {
        float t0 = INF_F, t1 = INF_F, t2 = INF_F, t3 = INF_F, t4 = INF_F;
        const float* p = g_d + (size_t)rowBase * KC + t;
#pragma unroll 8
        for (int r = 0; r < 128; r++)
            ins5(p[(size_t)r * KC], t0, t1, t2, t3, t4);
        float* pp = g_part1 + (size_t)blockIdx.x * 5 * KC + t;
        pp[0 * KC] = t0; pp[1 * KC] = t1; pp[2 * KC] = t2;
        pp[3 * KC] = t3; pp[4 * KC] = t4;
    }
}

// ---------------- bisection (mirrors reference update rule) -----------------
__device__ __forceinline__ float calibrate(float a1, float a2, float a3, float a4,
                                           float target) {
    float mid0 = 0.f, mid1 = SIGMA_HI_V, sigma = 1.f;
#pragma unroll 1
    for (int it = 0; it < CAL_ITERS; it++) {
        float inv = __frcp_rn(sigma);
        float cur = 1.f + __expf(-a1 * inv) + __expf(-a2 * inv) +
                    __expf(-a3 * inv) + __expf(-a4 * inv);
        if (cur > target) mid1 = sigma; else mid0 = sigma;
        sigma = 0.5f * (mid0 + mid1);
    }
    return sigma;
}

// ---------------- K3: fused reductions ---------------------------------------
__global__ __launch_bounds__(256) void k_reduce() {
    int b = blockIdx.x;
    if (b < 32) {
        int w = threadIdx.x >> 5, lane = threadIdx.x & 31;
        int col = b * 8 + w;
        float t0 = INF_F, t1 = INF_F, t2 = INF_F, t3 = INF_F, t4 = INF_F;
        for (int p = lane; p < NPART; p += 32) {
            const float* pp = g_part1 + (size_t)p * 5 * KC + col;
#pragma unroll
            for (int s = 0; s < 5; s++) ins5(pp[s * KC], t0, t1, t2, t3, t4);
        }
#pragma unroll
        for (int off = 16; off; off >>= 1) {
            float o0 = __shfl_xor_sync(0xffffffffu, t0, off);
            float o1 = __shfl_xor_sync(0xffffffffu, t1, off);
            float o2 = __shfl_xor_sync(0xffffffffu, t2, off);
            float o3 = __shfl_xor_sync(0xffffffffu, t3, off);
            float o4 = __shfl_xor_sync(0xffffffffu, t4, off);
            ins5(o0, t0, t1, t2, t3, t4);
            ins5(o1, t0, t1, t2, t3, t4);
            ins5(o2, t0, t1, t2, t3, t4);
            ins5(o3, t0, t1, t2, t3, t4);
            ins5(o4, t0, t1, t2, t3, t4);
        }
        if (lane == 0) {
            float rho = t0;
            g_rhou[col] = rho;
            g_colsum[col] = 0.f;
            float a1 = fmaxf(t1 - rho, 0.f), a2 = fmaxf(t2 - rho, 0.f);
            float a3 = fmaxf(t3 - rho, 0.f), a4 = fmaxf(t4 - rho, 0.f);
            g_sigu[col] = calibrate(a1, a2, a3, a4, TARGET_U);
        }
    } else {
        int row = (b - 32) * 256 + threadIdx.x;
        const float* r = g_relz + (size_t)row * 5;
        float rho = r[0];
        float a1 = fmaxf(r[1] - rho, 0.f), a2 = fmaxf(r[2] - rho, 0.f);
        float a3 = fmaxf(r[3] - rho, 0.f), a4 = fmaxf(r[4] - rho, 0.f);
        g_rhoz[row] = rho;
        g_sigz[row] = calibrate(a1, a2, a3, a4, TARGET_Z);
    }
}

// ---------------- K4: W1 / W2 / S + colsum (warp per row, float4 I/O) --------
__global__ __launch_bounds__(256) void k_ws(float* __restrict__ out) {
    __shared__ float s_rho[KC], s_isu[KC], s_cs[KC];
    int t = threadIdx.x;
    s_rho[t] = g_rhou[t];
    s_isu[t] = 1.0f / g_sigu[t];
    s_cs[t] = 0.f;
    __syncthreads();

    int lane = t & 31;
    int w = t >> 5;
    int wid = (blockIdx.x << 3) + w;
    const int wstride = gridDim.x << 3;
    const int c0 = lane * 4, c1 = 128 + lane * 4;
    float* outW1a = out;
    float* outS   = out + NKSZ;
    float* outW1b = out + 2 * NKSZ;

    float ru[8], iu[8];
#pragma unroll
    for (int j = 0; j < 4; j++) {
        ru[j] = s_rho[c0 + j];     iu[j] = s_isu[c0 + j];
        ru[4 + j] = s_rho[c1 + j]; iu[4 + j] = s_isu[c1 + j];
    }
    float cs[8];
#pragma unroll
    for (int j = 0; j < 8; j++) cs[j] = 0.f;

    for (int row = wid; row < NROWS; row += wstride) {
        float rho = g_rhoz[row];
        float isz = 1.0f / g_sigz[row];
        const float* dr = g_d + (size_t)row * KC;
        float4 d0 = *(const float4*)(dr + c0);
        float4 d1 = *(const float4*)(dr + c1);
        float dv[8] = {d0.x, d0.y, d0.z, d0.w, d1.x, d1.y, d1.z, d1.w};
        float w1v[8], sv[8];
        float sum = 0.f;
#pragma unroll
        for (int j = 0; j < 8; j++) {
            float w1 = __expf(-fmaxf(dv[j] - rho, 0.f) * isz);
            float w2 = __expf(-fmaxf(dv[j] - ru[j], 0.f) * iu[j]);
            float s = w1 + w2 - w1 * w2;
            w1v[j] = w1; sv[j] = s; sum += s;
        }
#pragma unroll
        for (int off = 16; off; off >>= 1) sum += __shfl_xor_sync(0xffffffffu, sum, off);
        float rinv = 1.0f / sum;
        float4 w1a = make_float4(w1v[0], w1v[1], w1v[2], w1v[3]);
        float4 w1b = make_float4(w1v[4], w1v[5], w1v[6], w1v[7]);
        float4 s0 = make_float4(sv[0] * rinv, sv[1] * rinv, sv[2] * rinv, sv[3] * rinv);
        float4 s1 = make_float4(sv[4] * rinv, sv[5] * rinv, sv[6] * rinv, sv[7] * rinv);
        size_t base = (size_t)row * KC;
        *(float4*)(outW1a + base + c0) = w1a;
        *(float4*)(outW1a + base + c1) = w1b;
        *(float4*)(outW1b + base + c0) = w1a;
        *(float4*)(outW1b + base + c1) = w1b;
        *(float4*)(outS + base + c0) = s0;
        *(float4*)(outS + base + c1) = s1;
        cs[0] += s0.x; cs[1] += s0.y; cs[2] += s0.z; cs[3] += s0.w;
        cs[4] += s1.x; cs[5] += s1.y; cs[6] += s1.z; cs[7] += s1.w;
    }
#pragma unroll
    for (int j = 0; j < 4; j++) {
        atomicAdd(&s_cs[c0 + j], cs[j]);
        atomicAdd(&s_cs[c1 + j], cs[4 + j]);
    }
    __syncthreads();
    atomicAdd(&g_colsum[t], s_cs[t]);
}

// ---------------- K5: Dmat (float4 I/O) ---------------------------------------
__global__ __launch_bounds__(256) void k_dmat(float* __restrict__ out) {
    __shared__ float s_ic[KC];
    int t = threadIdx.x;
    s_ic[t] = 1.0f / g_colsum[t];
    __syncthreads();

    const float* Sm = out + NKSZ;
    float* Dm = out + 3 * NKSZ;
    int lane = t & 31;
    int w = t >> 5;
    int wid = (blockIdx.x << 3) + w;
    const int wstride = gridDim.x << 3;
    const int c0 = lane * 4, c1 = 128 + lane * 4;

    float ic[8];
#pragma unroll
    for (int j = 0; j < 4; j++) {
        ic[j] = s_ic[c0 + j];
        ic[4 + j] = s_ic[c1 + j];
    }

    for (int row = wid; row < NROWS; row += wstride) {
        const float* sr = Sm + (size_t)row * KC;
        float4 v0 = *(const float4*)(sr + c0);
        float4 v1 = *(const float4*)(sr + c1);
        float sv[8] = {v0.x, v0.y, v0.z, v0.w, v1.x, v1.y, v1.z, v1.w};
        float tv[8];
        float sum = 0.f;
#pragma unroll
        for (int j = 0; j < 8; j++) {
            float q = sv[j] * sv[j] * ic[j];
            tv[j] = q; sum += q;
        }
#pragma unroll
        for (int off = 16; off; off >>= 1) sum += __shfl_xor_sync(0xffffffffu, sum, off);
        float rinv = 1.0f / sum;
        float4 o0 = make_float4(tv[0] * rinv, tv[1] * rinv, tv[2] * rinv, tv[3] * rinv);
        float4 o1 = make_float4(tv[4] * rinv, tv[5] * rinv, tv[6] * rinv, tv[7] * rinv);
        size_t base = (size_t)row * KC;
        *(float4*)(Dm + base + c0) = o0;
        *(float4*)(Dm + base + c1) = o1;
    }
}

// ---------------- launcher ---------------------------------------------------
extern "C" void kernel_launch(void* const* d_in, const int* in_sizes, int n_in,
                              void* d_out, int out_size) {
    (void)in_sizes; (void)n_in; (void)out_size;
    const float* z  = (const float*)d_in[0];
    const float* mu = (const float*)d_in[1];
    float* out = (float*)d_out;

    cudaFuncSetAttribute(k_gemm, cudaFuncAttributeMaxDynamicSharedMemorySize,
                         GSMEM_TOTAL);

    k_prep_mu<<<32, 256>>>(mu);                      // #1
    k_noop<<<1, 32>>>();                             // #2
    k_noop<<<1, 32>>>();                             // #3
    k_gemm<<<NROWS / 128, 512, GSMEM_TOTAL>>>(z);    // #4 <- ncu slot
    k_top<<<NROWS / 128, 256>>>();                   // #5
    k_reduce<<<288, 256>>>();                        // #6
    k_ws<<<1024, 256>>>(out);                        // #7
    k_dmat<<<1024, 256>>>(out);                      // #8
}

// round 15
// speedup vs baseline: 1.7602x; 1.0357x over previous
#include <cuda_runtime.h>
#include <cuda_bf16.h>
#include <math.h>
#include <stdint.h>

#define NROWS 65536
#define KC 256
#define DH 256
#define NKSZ ((size_t)NROWS * KC)
#define EPSV 1e-6f
#define SIGMA_HI_V 10000.0f
#define TARGET_Z 1.3219281f   /* log2(5)-1 */
#define TARGET_U 2.3219281f   /* log2(5)   */
#define INF_F __int_as_float(0x7f800000)
#define CAL_ITERS 64
#define NPART 512

// ---------------- scratch (device globals; no runtime allocation) ----------
__device__ float g_d[NKSZ];                 // 64MB distance matrix
__device__ uint4 g_mhi4[KC * 64];           // mu hi tf32-in-f32 (16B quads)
__device__ uint4 g_mlo4[KC * 64];           // mu lo tf32-in-f32
__device__ float g_m2[KC], g_ms[KC];
__device__ float g_relz[(size_t)NROWS * 5];
__device__ float g_rhoz[NROWS];
__device__ float g_sigz[NROWS];
__device__ float g_part1[NPART * 5 * KC];   // [cta][s][col]
__device__ float g_rhou[KC];
__device__ float g_sigu[KC];
__device__ float g_colsum[KC];

// ---------------- PTX helpers (baseline PTX only) ----------------------------
__device__ __forceinline__ uint32_t smem_u32(const void* p) {
    uint32_t a;
    asm("{ .reg .u64 t; cvta.to.shared.u64 t, %1; cvt.u32.u64 %0, t; }" : "=r"(a) : "l"(p));
    return a;
}

__device__ __forceinline__ uint32_t tf32u(float x) {
    uint32_t u;
    asm("cvt.rna.tf32.f32 %0, %1;" : "=r"(u) : "f"(x));
    return u;
}

__device__ __forceinline__ void ldmx4(uint32_t* r, uint32_t addr) {
    asm volatile("ldmatrix.sync.aligned.m8n8.x4.shared.b16 {%0,%1,%2,%3}, [%4];"
                 : "=r"(r[0]), "=r"(r[1]), "=r"(r[2]), "=r"(r[3]) : "r"(addr));
}

__device__ __forceinline__ void mma_tf32(float* d, const uint32_t* a, const uint32_t* b) {
    asm volatile(
        "mma.sync.aligned.m16n8k8.row.col.f32.tf32.tf32.f32 "
        "{%0,%1,%2,%3}, {%4,%5,%6,%7}, {%8,%9}, {%0,%1,%2,%3};"
        : "+f"(d[0]), "+f"(d[1]), "+f"(d[2]), "+f"(d[3])
        : "r"(a[0]), "r"(a[1]), "r"(a[2]), "r"(a[3]), "r"(b[0]), "r"(b[1]));
}

__device__ __forceinline__ void cpa16(uint32_t dst, const void* src) {
    asm volatile("cp.async.cg.shared.global [%0], [%1], 16;"
                 :: "r"(dst), "l"(__cvta_generic_to_global(src)));
}

// ---------------- K0: mu prep (warp per row; parallel) ------------------------
__global__ __launch_bounds__(256) void k_prep_mu(const float* __restrict__ mu) {
    int row = blockIdx.x * 8 + (threadIdx.x >> 5);
    int lane = threadIdx.x & 31;
    const float* r = mu + (size_t)row * DH + lane * 8;
    float m2 = 0.f, ms = 0.f;
#pragma unroll
    for (int g = 0; g < 2; g++) {
        float4 v = *(const float4*)(r + g * 4);
        float x[4] = {v.x, v.y, v.z, v.w};
        uint32_t hi[4], lo[4];
#pragma unroll
        for (int q = 0; q < 4; q++) {
            m2 = fmaf(x[q], x[q], m2);
            ms += x[q];
            hi[q] = tf32u(x[q]);
            lo[q] = tf32u(x[q] - __uint_as_float(hi[q]));
        }
        g_mhi4[row * 64 + lane * 2 + g] = make_uint4(hi[0], hi[1], hi[2], hi[3]);
        g_mlo4[row * 64 + lane * 2 + g] = make_uint4(lo[0], lo[1], lo[2], lo[3]);
    }
#pragma unroll
    for (int off = 16; off; off >>= 1) {
        m2 += __shfl_xor_sync(0xffffffffu, m2, off);
        ms += __shfl_xor_sync(0xffffffffu, ms, off);
    }
    if (lane == 0) { g_m2[row] = m2; g_ms[row] = ms; }
}

__global__ void k_noop() {}

// ---------------- insertion helper ------------------------------------------
__device__ __forceinline__ void ins5(float v, float &t0, float &t1, float &t2,
                                     float &t3, float &t4) {
    if (v < t4) {
        if (v < t3) {
            t4 = t3;
            if (v < t2) {
                t3 = t2;
                if (v < t1) {
                    t2 = t1;
                    if (v < t0) { t1 = t0; t0 = v; } else t1 = v;
                } else t2 = v;
            } else t3 = v;
        } else t4 = v;
    }
}

// ---------------- K1: LEAN tf32-split GEMM + d, cp.async B double-buffer -----
// CTA 128x256, 16 warps, warp tile 32x64. K in 8 chunks of 32, 4 k8-steps each.
// B (pre-split hi/lo) streamed global->smem via cp.async, 2 stages.
#define LDS_A 36
#define TILE_LD 260
#define SA_HI 0
#define SA_LO 18432
#define SB_BASE 36864                  /* stage s hi: +s*73728; lo: +36864 */
#define SB_STAGE 73728
#define ST_M2 184320
#define ST_MS 185344
#define ST_Z2 186368
#define ST_ZS 186880
#define GSMEM_TOTAL 187392

__device__ __forceinline__ void issue_B(uint32_t sbase, int c, int t) {
    // 2048 uint4 per half (256 rows x 8 quads); 512 threads -> 4 each per half
#pragma unroll
    for (int i = 0; i < 4; i++) {
        int e = t + 512 * i;             // 0..2047
        int row = e >> 3, q = e & 7;
        uint32_t off = ((uint32_t)row * LDS_A + q * 4) * 4;
        cpa16(sbase + off, &g_mhi4[row * 64 + c * 8 + q]);
        cpa16(sbase + SB_STAGE / 2 + off, &g_mlo4[row * 64 + c * 8 + q]);
    }
    asm volatile("cp.async.commit_group;");
}

__global__ __launch_bounds__(512, 1) void k_gemm(const float* __restrict__ z) {
    extern __shared__ char smem[];
    const uint32_t sb = smem_u32(smem);
    const int t = threadIdx.x;
    const int wid = t >> 5, lane = t & 31;
    const int wr = wid >> 2, wc = wid & 3;
    const int rowBase = blockIdx.x * 128;

    float* s_m2 = (float*)(smem + ST_M2);
    float* s_ms = (float*)(smem + ST_MS);
    float* s_z2 = (float*)(smem + ST_Z2);
    float* s_zs = (float*)(smem + ST_ZS);
    if (t < 256) { s_m2[t] = g_m2[t]; s_ms[t] = g_ms[t]; }

    float acc[2][8][4];
#pragma unroll
    for (int mt = 0; mt < 2; mt++)
#pragma unroll
        for (int j = 0; j < 8; j++)
#pragma unroll
            for (int q = 0; q < 4; q++) acc[mt][j][q] = 0.f;

    const int ar = t >> 2, aq = t & 3;
    const float* zrow = z + (size_t)(rowBase + ar) * DH + aq * 8;
    float z2p = 0.f, zsp = 0.f;

    const uint32_t a_off = ((uint32_t)(wr * 32 + (lane & 15)) * LDS_A +
                            ((lane >> 4) << 2)) * 4;
    const uint32_t b_off = ((uint32_t)(wc * 64 + ((lane >> 4) << 3) + (lane & 7)) * LDS_A +
                            ((lane & 8) >> 1)) * 4;

    // prologue: prefetch B chunk 0 into stage 0
    issue_B(sb + SB_BASE, 0, t);

#pragma unroll 1
    for (int c = 0; c < 8; c++) {
        __syncthreads();   // A buffer free (prev chunk's LDSM done)
        // ---- A: 8 f32 per thread, split to hi/lo tf32, STS ------------------
        {
            const float4* src = (const float4*)(zrow + c * 32);
            float4 v0 = src[0], v1 = src[1];
            float xs[8] = {v0.x, v0.y, v0.z, v0.w, v1.x, v1.y, v1.z, v1.w};
            float hi[8], lo[8];
#pragma unroll
            for (int q = 0; q < 8; q++) {
                z2p = fmaf(xs[q], xs[q], z2p);
                zsp += xs[q];
                uint32_t h = tf32u(xs[q]);
                hi[q] = __uint_as_float(h);
                lo[q] = __uint_as_float(tf32u(xs[q] - hi[q]));
            }
            uint32_t off = ((uint32_t)ar * LDS_A + aq * 8) * 4;
            *(float4*)(smem + SA_HI + off)      = make_float4(hi[0], hi[1], hi[2], hi[3]);
            *(float4*)(smem + SA_HI + off + 16) = make_float4(hi[4], hi[5], hi[6], hi[7]);
            *(float4*)(smem + SA_LO + off)      = make_float4(lo[0], lo[1], lo[2], lo[3]);
            *(float4*)(smem + SA_LO + off + 16) = make_float4(lo[4], lo[5], lo[6], lo[7]);
        }
        // ---- prefetch next B chunk into other stage --------------------------
        if (c < 7) {
            issue_B(sb + SB_BASE + ((c + 1) & 1) * SB_STAGE, c + 1, t);
            asm volatile("cp.async.wait_group 1;");  // B[c] complete
        } else {
            asm volatile("cp.async.wait_group 0;");
        }
        __syncthreads();   // A visible to all; B wait uniform

        const uint32_t bh_base = sb + SB_BASE + (c & 1) * SB_STAGE;
        const uint32_t bl_base = bh_base + SB_STAGE / 2;

        // ---- mma over 4 k8-steps, full-width passes --------------------------
#pragma unroll
        for (int ks = 0; ks < 4; ks++) {
            const uint32_t kb = (uint32_t)ks * 32;
            uint32_t ah[2][4], al[2][4];
            ldmx4(ah[0], sb + SA_HI + a_off + kb);
            ldmx4(ah[1], sb + SA_HI + a_off + kb + 16 * LDS_A * 4);
            ldmx4(al[0], sb + SA_LO + a_off + kb);
            ldmx4(al[1], sb + SA_LO + a_off + kb + 16 * LDS_A * 4);

            uint32_t bh[4][4];
#pragma unroll
            for (int p = 0; p < 4; p++)
                ldmx4(bh[p], bh_base + b_off + kb + (uint32_t)p * 16 * LDS_A * 4);
#pragma unroll
            for (int p = 0; p < 4; p++) {
                mma_tf32(acc[0][2 * p],     ah[0], &bh[p][0]);
                mma_tf32(acc[0][2 * p + 1], ah[0], &bh[p][2]);
                mma_tf32(acc[1][2 * p],     ah[1], &bh[p][0]);
                mma_tf32(acc[1][2 * p + 1], ah[1], &bh[p][2]);
            }
#pragma unroll
            for (int p = 0; p < 4; p++) {
                mma_tf32(acc[0][2 * p],     al[0], &bh[p][0]);
                mma_tf32(acc[0][2 * p + 1], al[0], &bh[p][2]);
                mma_tf32(acc[1][2 * p],     al[1], &bh[p][0]);
                mma_tf32(acc[1][2 * p + 1], al[1], &bh[p][2]);
            }
            uint32_t bl[4][4];
#pragma unroll
            for (int p = 0; p < 4; p++)
                ldmx4(bl[p], bl_base + b_off + kb + (uint32_t)p * 16 * LDS_A * 4);
#pragma unroll
            for (int p = 0; p < 4; p++) {
                mma_tf32(acc[0][2 * p],     ah[0], &bl[p][0]);
                mma_tf32(acc[0][2 * p + 1], ah[0], &bl[p][2]);
                mma_tf32(acc[1][2 * p],     ah[1], &bl[p][0]);
                mma_tf32(acc[1][2 * p + 1], ah[1], &bl[p][2]);
            }
        }
    }

    z2p += __shfl_xor_sync(0xffffffffu, z2p, 1);
    z2p += __shfl_xor_sync(0xffffffffu, z2p, 2);
    zsp += __shfl_xor_sync(0xffffffffu, zsp, 1);
    zsp += __shfl_xor_sync(0xffffffffu, zsp, 2);
    if (aq == 0) { s_z2[ar] = z2p; s_zs[ar] = zsp; }
    __syncthreads();

    float* tile = (float*)smem;
    const float cterm = (float)DH * EPSV * EPSV;
#pragma unroll
    for (int mt = 0; mt < 2; mt++) {
        const int r0 = wr * 32 + mt * 16 + (lane >> 2);
        const float z2va = s_z2[r0], zsva = s_zs[r0];
        const float z2vb = s_z2[r0 + 8], zsvb = s_zs[r0 + 8];
#pragma unroll
        for (int nt = 0; nt < 8; nt++) {
            const int c0 = wc * 64 + nt * 8 + (lane & 3) * 2;
            float m20 = s_m2[c0], ms0 = s_ms[c0];
            float m21 = s_m2[c0 + 1], ms1 = s_ms[c0 + 1];
            float d00 = z2va + m20 - 2.f * acc[mt][nt][0] + 2.f * EPSV * (zsva - ms0) + cterm;
            float d01 = z2va + m21 - 2.f * acc[mt][nt][1] + 2.f * EPSV * (zsva - ms1) + cterm;
            float d10 = z2vb + m20 - 2.f * acc[mt][nt][2] + 2.f * EPSV * (zsvb - ms0) + cterm;
            float d11 = z2vb + m21 - 2.f * acc[mt][nt][3] + 2.f * EPSV * (zsvb - ms1) + cterm;
            tile[r0 * TILE_LD + c0]           = sqrtf(fmaxf(d00, 0.f));
            tile[r0 * TILE_LD + c0 + 1]       = sqrtf(fmaxf(d01, 0.f));
            tile[(r0 + 8) * TILE_LD + c0]     = sqrtf(fmaxf(d10, 0.f));
            tile[(r0 + 8) * TILE_LD + c0 + 1] = sqrtf(fmaxf(d11, 0.f));
        }
    }
    __syncthreads();

#pragma unroll
    for (int i = 0; i < 16; i++) {
        int e = t + 512 * i;
        int row = e >> 6, c4 = e & 63;
        float4 v = *(const float4*)&tile[row * TILE_LD + c4 * 4];
        *(float4*)&g_d[(size_t)(rowBase + row) * KC + c4 * 4] = v;
    }
}

// ---------------- K2: top-5 reductions over g_d (row + column partials) ------
__global__ __launch_bounds__(256) void k_top() {
    const int rowBase = blockIdx.x * 128;
    const int t = threadIdx.x;
    const int w = t >> 5, lane = t & 31;

#pragma unroll 1
    for (int rr = 0; rr < 16; rr++) {
        int row = rowBase + w * 16 + rr;
        const float* dr = g_d + (size_t)row * KC;
        float4 d0 = *(const float4*)(dr + lane * 4);
        float4 d1 = *(const float4*)(dr + 128 + lane * 4);
        float t0 = INF_F, t1 = INF_F, t2 = INF_F, t3 = INF_F, t4 = INF_F;
        ins5(d0.x, t0, t1, t2, t3, t4); ins5(d0.y, t0, t1, t2, t3, t4);
        ins5(d0.z, t0, t1, t2, t3, t4); ins5(d0.w, t0, t1, t2, t3, t4);
        ins5(d1.x, t0, t1, t2, t3, t4); ins5(d1.y, t0, t1, t2, t3, t4);
        ins5(d1.z, t0, t1, t2, t3, t4); ins5(d1.w, t0, t1, t2, t3, t4);
#pragma unroll
        for (int off = 16; off; off >>= 1) {
            float o0 = __shfl_xor_sync(0xffffffffu, t0, off);
            float o1 = __shfl_xor_sync(0xffffffffu, t1, off);
            float o2 = __shfl_xor_sync(0xffffffffu, t2, off);
            float o3 = __shfl_xor_sync(0xffffffffu, t3, off);
            float o4 = __shfl_xor_sync(0xffffffffu, t4, off);
            ins5(o0, t0, t1, t2, t3, t4);
            ins5(o1, t0, t1, t2, t3, t4);
            ins5(o2, t0, t1, t2, t3, t4);
            ins5(o3, t0, t1, t2, t3, t4);
            ins5(o4, t0, t1, t2, t3, t4);
        }
        if (lane == 0) {
            float* rp = g_relz + (size_t)row * 5;
            rp[0] = t0; rp[1] = t1; rp[2] = t2; rp[3] = t3; rp[4] = t4;
        }
    }

    {
        float t0 = INF_F, t1 = INF_F, t2 = INF_F, t3 = INF_F, t4 = INF_F;
        const float* p = g_d + (size_t)rowBase * KC + t;
#pragma unroll 8
        for (int r = 0; r < 128; r++)
            ins5(p[(size_t)r * KC], t0, t1, t2, t3, t4);
        float* pp = g_part1 + (size_t)blockIdx.x * 5 * KC + t;
        pp[0 * KC] = t0; pp[1 * KC] = t1; pp[2 * KC] = t2;
        pp[3 * KC] = t3; pp[4 * KC] = t4;
    }
}

// ---------------- bisection (mirrors reference update rule) -----------------
__device__ __forceinline__ float calibrate(float a1, float a2, float a3, float a4,
                                           float target) {
    float mid0 = 0.f, mid1 = SIGMA_HI_V, sigma = 1.f;
#pragma unroll 1
    for (int it = 0; it < CAL_ITERS; it++) {
        float inv = __frcp_rn(sigma);
        float cur = 1.f + __expf(-a1 * inv) + __expf(-a2 * inv) +
                    __expf(-a3 * inv) + __expf(-a4 * inv);
        if (cur > target) mid1 = sigma; else mid0 = sigma;
        sigma = 0.5f * (mid0 + mid1);
    }
    return sigma;
}

// ---------------- K3: fused reductions ---------------------------------------
__global__ __launch_bounds__(256) void k_reduce() {
    int b = blockIdx.x;
    if (b < 32) {
        int w = threadIdx.x >> 5, lane = threadIdx.x & 31;
        int col = b * 8 + w;
        float t0 = INF_F, t1 = INF_F, t2 = INF_F, t3 = INF_F, t4 = INF_F;
        for (int p = lane; p < NPART; p += 32) {
            const float* pp = g_part1 + (size_t)p * 5 * KC + col;
#pragma unroll
            for (int s = 0; s < 5; s++) ins5(pp[s * KC], t0, t1, t2, t3, t4);
        }
#pragma unroll
        for (int off = 16; off; off >>= 1) {
            float o0 = __shfl_xor_sync(0xffffffffu, t0, off);
            float o1 = __shfl_xor_sync(0xffffffffu, t1, off);
            float o2 = __shfl_xor_sync(0xffffffffu, t2, off);
            float o3 = __shfl_xor_sync(0xffffffffu, t3, off);
            float o4 = __shfl_xor_sync(0xffffffffu, t4, off);
            ins5(o0, t0, t1, t2, t3, t4);
            ins5(o1, t0, t1, t2, t3, t4);
            ins5(o2, t0, t1, t2, t3, t4);
            ins5(o3, t0, t1, t2, t3, t4);
            ins5(o4, t0, t1, t2, t3, t4);
        }
        if (lane == 0) {
            float rho = t0;
            g_rhou[col] = rho;
            g_colsum[col] = 0.f;
            float a1 = fmaxf(t1 - rho, 0.f), a2 = fmaxf(t2 - rho, 0.f);
            float a3 = fmaxf(t3 - rho, 0.f), a4 = fmaxf(t4 - rho, 0.f);
            g_sigu[col] = calibrate(a1, a2, a3, a4, TARGET_U);
        }
    } else {
        int row = (b - 32) * 256 + threadIdx.x;
        const float* r = g_relz + (size_t)row * 5;
        float rho = r[0];
        float a1 = fmaxf(r[1] - rho, 0.f), a2 = fmaxf(r[2] - rho, 0.f);
        float a3 = fmaxf(r[3] - rho, 0.f), a4 = fmaxf(r[4] - rho, 0.f);
        g_rhoz[row] = rho;
        g_sigz[row] = calibrate(a1, a2, a3, a4, TARGET_Z);
    }
}

// ---------------- K4: W1 / W2 / S + colsum (warp per row, float4 I/O) --------
__global__ __launch_bounds__(256) void k_ws(float* __restrict__ out) {
    __shared__ float s_rho[KC], s_isu[KC], s_cs[KC];
    int t = threadIdx.x;
    s_rho[t] = g_rhou[t];
    s_isu[t] = 1.0f / g_sigu[t];
    s_cs[t] = 0.f;
    __syncthreads();

    int lane = t & 31;
    int w = t >> 5;
    int wid = (blockIdx.x << 3) + w;
    const int wstride = gridDim.x << 3;
    const int c0 = lane * 4, c1 = 128 + lane * 4;
    float* outW1a = out;
    float* outS   = out + NKSZ;
    float* outW1b = out + 2 * NKSZ;

    float ru[8], iu[8];
#pragma unroll
    for (int j = 0; j < 4; j++) {
        ru[j] = s_rho[c0 + j];     iu[j] = s_isu[c0 + j];
        ru[4 + j] = s_rho[c1 + j]; iu[4 + j] = s_isu[c1 + j];
    }
    float cs[8];
#pragma unroll
    for (int j = 0; j < 8; j++) cs[j] = 0.f;

    for (int row = wid; row < NROWS; row += wstride) {
        float rho = g_rhoz[row];
        float isz = 1.0f / g_sigz[row];
        const float* dr = g_d + (size_t)row * KC;
        float4 d0 = *(const float4*)(dr + c0);
        float4 d1 = *(const float4*)(dr + c1);
        float dv[8] = {d0.x, d0.y, d0.z, d0.w, d1.x, d1.y, d1.z, d1.w};
        float w1v[8], sv[8];
        float sum = 0.f;
#pragma unroll
        for (int j = 0; j < 8; j++) {
            float w1 = __expf(-fmaxf(dv[j] - rho, 0.f) * isz);
            float w2 = __expf(-fmaxf(dv[j] - ru[j], 0.f) * iu[j]);
            float s = w1 + w2 - w1 * w2;
            w1v[j] = w1; sv[j] = s; sum += s;
        }
#pragma unroll
        for (int off = 16; off; off >>= 1) sum += __shfl_xor_sync(0xffffffffu, sum, off);
        float rinv = 1.0f / sum;
        float4 w1a = make_float4(w1v[0], w1v[1], w1v[2], w1v[3]);
        float4 w1b = make_float4(w1v[4], w1v[5], w1v[6], w1v[7]);
        float4 s0 = make_float4(sv[0] * rinv, sv[1] * rinv, sv[2] * rinv, sv[3] * rinv);
        float4 s1 = make_float4(sv[4] * rinv, sv[5] * rinv, sv[6] * rinv, sv[7] * rinv);
        size_t base = (size_t)row * KC;
        *(float4*)(outW1a + base + c0) = w1a;
        *(float4*)(outW1a + base + c1) = w1b;
        *(float4*)(outW1b + base + c0) = w1a;
        *(float4*)(outW1b + base + c1) = w1b;
        *(float4*)(outS + base + c0) = s0;
        *(float4*)(outS + base + c1) = s1;
        cs[0] += s0.x; cs[1] += s0.y; cs[2] += s0.z; cs[3] += s0.w;
        cs[4] += s1.x; cs[5] += s1.y; cs[6] += s1.z; cs[7] += s1.w;
    }
#pragma unroll
    for (int j = 0; j < 4; j++) {
        atomicAdd(&s_cs[c0 + j], cs[j]);
        atomicAdd(&s_cs[c1 + j], cs[4 + j]);
    }
    __syncthreads();
    atomicAdd(&g_colsum[t], s_cs[t]);
}

// ---------------- K5: Dmat (float4 I/O) ---------------------------------------
__global__ __launch_bounds__(256) void k_dmat(float* __restrict__ out) {
    __shared__ float s_ic[KC];
    int t = threadIdx.x;
    s_ic[t] = 1.0f / g_colsum[t];
    __syncthreads();

    const float* Sm = out + NKSZ;
    float* Dm = out + 3 * NKSZ;
    int lane = t & 31;
    int w = t >> 5;
    int wid = (blockIdx.x << 3) + w;
    const int wstride = gridDim.x << 3;
    const int c0 = lane * 4, c1 = 128 + lane * 4;

    float ic[8];
#pragma unroll
    for (int j = 0; j < 4; j++) {
        ic[j] = s_ic[c0 + j];
        ic[4 + j] = s_ic[c1 + j];
    }

    for (int row = wid; row < NROWS; row += wstride) {
        const float* sr = Sm + (size_t)row * KC;
        float4 v0 = *(const float4*)(sr + c0);
        float4 v1 = *(const float4*)(sr + c1);
        float sv[8] = {v0.x, v0.y, v0.z, v0.w, v1.x, v1.y, v1.z, v1.w};
        float tv[8];
        float sum = 0.f;
#pragma unroll
        for (int j = 0; j < 8; j++) {
            float q = sv[j] * sv[j] * ic[j];
            tv[j] = q; sum += q;
        }
#pragma unroll
        for (int off = 16; off; off >>= 1) sum += __shfl_xor_sync(0xffffffffu, sum, off);
        float rinv = 1.0f / sum;
        float4 o0 = make_float4(tv[0] * rinv, tv[1] * rinv, tv[2] * rinv, tv[3] * rinv);
        float4 o1 = make_float4(tv[4] * rinv, tv[5] * rinv, tv[6] * rinv, tv[7] * rinv);
        size_t base = (size_t)row * KC;
        *(float4*)(Dm + base + c0) = o0;
        *(float4*)(Dm + base + c1) = o1;
    }
}

// ---------------- launcher ---------------------------------------------------
extern "C" void kernel_launch(void* const* d_in, const int* in_sizes, int n_in,
                              void* d_out, int out_size) {
    (void)in_sizes; (void)n_in; (void)out_size;
    const float* z  = (const float*)d_in[0];
    const float* mu = (const float*)d_in[1];
    float* out = (float*)d_out;

    cudaFuncSetAttribute(k_gemm, cudaFuncAttributeMaxDynamicSharedMemorySize,
                         GSMEM_TOTAL);

    k_prep_mu<<<32, 256>>>(mu);                      // #1
    k_noop<<<1, 32>>>();                             // #2
    k_noop<<<1, 32>>>();                             // #3
    k_gemm<<<NROWS / 128, 512, GSMEM_TOTAL>>>(z);    // #4 <- ncu slot
    k_top<<<NROWS / 128, 256>>>();                   // #5
    k_reduce<<<288, 256>>>();                        // #6
    k_ws<<<1024, 256>>>(out);                        // #7
    k_dmat<<<1024, 256>>>(out);                      // #8
}